// round 10
// baseline (speedup 1.0000x reference)
#include <cuda_runtime.h>
#include <cuda_fp16.h>

#define BB   16
#define SEQ  512
#define NH   8
#define DH   128
#define HD   1024
#define NROWS (BB*SEQ)            // 8192
#define SCALE 0.08838834764831843f

// Scratch (no device allocation allowed)
__device__ __half g_q  [BB*NH*SEQ*DH]; // [B,H,N,D] masked*scaled fp16
__device__ __half g_k  [BB*NH*SEQ*DH]; // [B,H,N,D] masked fp16
__device__ __half g_v  [BB*NH*SEQ*DH]; // [B,H,N,D] masked fp16
__device__ __half g_y1h[NROWS*HD];     // [B,N,H*D] attn out fp16
__device__ __half g_xh [NROWS*DH];     // x fp16
__device__ __half g_wqt[HD*DH];        // Wq^T [n][k] fp16
__device__ __half g_wkt[HD*DH];
__device__ __half g_wvt[HD*DH];
__device__ __half g_wot[DH*HD];        // Wo^T [n=128][k=1024] fp16

__device__ __forceinline__ void cpa16(void* dst_smem, const void* src_gmem) {
    unsigned s = (unsigned)__cvta_generic_to_shared(dst_smem);
    asm volatile("cp.async.cg.shared.global [%0], [%1], 16;\n" :: "r"(s), "l"(src_gmem));
}
#define CP_COMMIT() asm volatile("cp.async.commit_group;\n")
#define CP_WAIT(n)  asm volatile("cp.async.wait_group %0;\n" :: "n"(n))

// fp16 k16 mma, fp32 accum
__device__ __forceinline__ void mma16(float* d, const unsigned* a, const unsigned* b) {
    asm volatile(
        "mma.sync.aligned.m16n8k16.row.col.f32.f16.f16.f32 "
        "{%0,%1,%2,%3}, {%4,%5,%6,%7}, {%8,%9}, {%0,%1,%2,%3};"
        : "+f"(d[0]), "+f"(d[1]), "+f"(d[2]), "+f"(d[3])
        : "r"(a[0]), "r"(a[1]), "r"(a[2]), "r"(a[3]), "r"(b[0]), "r"(b[1]));
}
__device__ __forceinline__ unsigned smaddr(const void* p) {
    return (unsigned)__cvta_generic_to_shared(p);
}
__device__ __forceinline__ void ldsm4t(unsigned* r, unsigned a) {
    asm volatile("ldmatrix.sync.aligned.m8n8.x4.trans.shared.b16 {%0,%1,%2,%3}, [%4];"
        : "=r"(r[0]), "=r"(r[1]), "=r"(r[2]), "=r"(r[3]) : "r"(a));
}

// ---------------------------------------------------------------------------
// prep: x -> fp16. grid 1024 x 256
// ---------------------------------------------------------------------------
__global__ void prep_kernel(const float* __restrict__ x)
{
    int i = blockIdx.x * 256 + threadIdx.x;       // float4 index
    if (i < NROWS*DH/4) {
        float4 v = ((const float4*)x)[i];
        ((__half2*)g_xh)[i * 2 + 0] = __floats2half2_rn(v.x, v.y);
        ((__half2*)g_xh)[i * 2 + 1] = __floats2half2_rn(v.z, v.w);
    }
}

// ---------------------------------------------------------------------------
// weight transpose -> fp16: W[R=k][C=n] f32 -> Wt[C][R] h16. grid (32,32,4)
// ---------------------------------------------------------------------------
__global__ void wtrans_kernel(const float* __restrict__ Wq, const float* __restrict__ Wk,
                              const float* __restrict__ Wv, const float* __restrict__ Wo)
{
    __shared__ float t[32][33];
    const int z = blockIdx.z;
    const float* src = (z == 0) ? Wq : (z == 1) ? Wk : (z == 2) ? Wv : Wo;
    __half* dst = (z == 0) ? g_wqt : (z == 1) ? g_wkt : (z == 2) ? g_wvt : g_wot;
    const int R = (z < 3) ? DH : HD;
    const int C = (z < 3) ? HD : DH;
    if ((int)blockIdx.x * 32 >= C || (int)blockIdx.y * 32 >= R) return;
    const int tx = threadIdx.x, ty = threadIdx.y;
    const int r = blockIdx.y * 32, c = blockIdx.x * 32;
#pragma unroll
    for (int j = 0; j < 4; j++)
        t[ty + j*8][tx] = src[(size_t)(r + ty + j*8) * C + c + tx];
    __syncthreads();
#pragma unroll
    for (int j = 0; j < 4; j++)
        dst[(size_t)(c + ty + j*8) * R + r + tx] = __float2half_rn(t[tx][ty + j*8]);
}

// ---------------------------------------------------------------------------
// QKV projection fp16: out = (x @ W + b) * mask (* scale for q) -> fp16 [B,H,N,D]
// grid (HD/64, NROWS/128, 3), 256 thr (8 warps: wm 0..3 x 32 rows, wn 0..1 x
// 32 cols); CTA tile 128x64, K staged 64, double-buf, 4 CTAs/SM.
// smem/stage (halves): As[128][72] + Bs(Wt)[64][72] = 13824 h
// ---------------------------------------------------------------------------
#define PROJ_STG 13824
__global__ __launch_bounds__(256, 4) void proj_kernel(
    const float* __restrict__ mask,
    const float* __restrict__ bq, const float* __restrict__ bk,
    const float* __restrict__ bv)
{
    extern __shared__ __half smh[];
    const int tid = threadIdx.x;
    const int wid = tid >> 5, lane = tid & 31;
    const int g = lane >> 2, c = lane & 3;
    const int wm = wid & 3, wn = wid >> 2;       // warp tile 32 x 32
    const int c0 = blockIdx.x * 64;
    const int r0 = blockIdx.y * 128;
    const int sel = blockIdx.z;
    const __half* Wt  = (sel == 0) ? g_wqt : (sel == 1) ? g_wkt : g_wvt;
    const float* bias = (sel == 0) ? bq : (sel == 1) ? bk : bv;
    __half*      out  = (sel == 0) ? g_q : (sel == 1) ? g_k : g_v;
    const float extra = (sel == 0) ? SCALE : 1.0f;
    const __half* xbase = g_xh + (size_t)r0 * DH;
    const __half* wbase = Wt + (size_t)c0 * DH;

    const int frow = tid >> 3, fc8 = (tid & 7) * 8;   // 32 rows x 8 chunks
#define PROJ_FILL(ks, buf) {                                                    \
        __half* As = smh + (buf) * PROJ_STG;                                    \
        __half* Bs = As + 9216;                                                 \
        const int k0 = (ks) * 64;                                               \
        _Pragma("unroll")                                                       \
        for (int t = 0; t < 4; t++) {                                           \
            int row = frow + t * 32;                                            \
            cpa16(&As[row * 72 + fc8], &xbase[(size_t)row * DH + k0 + fc8]);    \
        }                                                                       \
        _Pragma("unroll")                                                       \
        for (int t = 0; t < 2; t++) {                                           \
            int row = frow + t * 32;                                            \
            cpa16(&Bs[row * 72 + fc8], &wbase[(size_t)row * DH + k0 + fc8]);    \
        }                                                                       \
        CP_COMMIT(); }

    float acc[2][4][4];
#pragma unroll
    for (int mf = 0; mf < 2; mf++)
#pragma unroll
        for (int nf = 0; nf < 4; nf++)
#pragma unroll
            for (int i = 0; i < 4; i++) acc[mf][nf][i] = 0.0f;

    PROJ_FILL(0, 0);
    for (int ks = 0; ks < 2; ks++) {
        if (ks < 1) { PROJ_FILL(1, 1); CP_WAIT(1); }
        else        { CP_WAIT(0); }
        __syncthreads();
        const __half* As = smh + (ks & 1) * PROJ_STG;
        const __half* Bs = As + 9216;
#pragma unroll
        for (int kb = 0; kb < 4; kb++) {
            const int k16 = kb * 16 + 2 * c;
            unsigned a[2][4];
#pragma unroll
            for (int mf = 0; mf < 2; mf++) {
                int row = wm * 32 + mf * 16;
                a[mf][0] = *(const unsigned*)&As[(row + g) * 72 + k16];
                a[mf][1] = *(const unsigned*)&As[(row + g + 8) * 72 + k16];
                a[mf][2] = *(const unsigned*)&As[(row + g) * 72 + k16 + 8];
                a[mf][3] = *(const unsigned*)&As[(row + g + 8) * 72 + k16 + 8];
            }
#pragma unroll
            for (int nf = 0; nf < 4; nf++) {
                int col = wn * 32 + nf * 8;
                unsigned b[2];
                b[0] = *(const unsigned*)&Bs[(col + g) * 72 + k16];
                b[1] = *(const unsigned*)&Bs[(col + g) * 72 + k16 + 8];
                mma16(acc[0][nf], a[0], b);
                mma16(acc[1][nf], a[1], b);
            }
        }
        __syncthreads();
    }

#pragma unroll
    for (int mf = 0; mf < 2; mf++) {
#pragma unroll
        for (int rr = 0; rr < 2; rr++) {
            int row = r0 + wm * 32 + mf * 16 + g + rr * 8;
            int bI = row >> 9, n = row & 511;
            float mm = mask[row] * extra;
#pragma unroll
            for (int nf = 0; nf < 4; nf++) {
                int col = c0 + wn * 32 + nf * 8 + 2 * c;
                int h = col >> 7, d = col & 127;
                float v0 = (acc[mf][nf][rr * 2 + 0] + bias[col]) * mm;
                float v1 = (acc[mf][nf][rr * 2 + 1] + bias[col + 1]) * mm;
                *(__half2*)&out[(((size_t)bI * NH + h) * SEQ + n) * DH + d] =
                    __floats2half2_rn(v0, v1);
            }
        }
    }
}

// ---------------------------------------------------------------------------
// Flash attention fp16, no-max softmax. dist read DIRECTLY (fp32, cp.async,
// double-buffered); key-mask applied additively at S-init from smem table.
// grid (SEQ/128, BB*NH), 1024 thr (32 warps: 8 row-groups x 4 quarters).
// smem: Qs/K2/V2 fp16, D2 fp32[2][128][68], Ps fp16, Msa f[512], Lp f[512]
//   = 122880 + 69632 + 2048 + 2048 = 196608 B
// ---------------------------------------------------------------------------
#define QSTR 136
#define PSTR 72
#define DSTR 68
__global__ __launch_bounds__(1024, 1) void attn_kernel(
    const float* __restrict__ dist, const float* __restrict__ mask)
{
    extern __shared__ __half smh[];
    __half* Qs = smh;                    // 17408 h
    __half* K2 = Qs + 128 * QSTR;        // 2 x 8704 h
    __half* V2 = K2 + 2 * 64 * QSTR;     // 2 x 8704 h
    __half* Ps = V2 + 2 * 64 * QSTR;     // 9216 h
    float*  D2 = (float*)(Ps + 128 * PSTR);  // 2 x 128*68 f
    float*  Msa = D2 + 2 * 128 * DSTR;   // 512 f additive key mask
    float*  Lp  = Msa + 512;             // 512 f

    const int tid = threadIdx.x;
    const int wid = tid >> 5, lane = tid & 31;
    const int g = lane >> 2, c = lane & 3;
    const int wm = wid & 7, wn = wid >> 3;   // 8 row-groups x 4 quarters
    const int bh = blockIdx.y;
    const int b = bh >> 3, h = bh & 7;
    const int q0 = blockIdx.x * 128;
    const int m0 = wm * 16;

    const __half* qbase = g_q + (size_t)bh * SEQ * DH;
    const __half* kbase = g_k + (size_t)bh * SEQ * DH;
    const __half* vbase = g_v + (size_t)bh * SEQ * DH;
    const float*  dbase = dist + ((size_t)b * SEQ + q0) * SEQ;

    const int frow = tid >> 4, fc8 = (tid & 15) * 8;   // K/V: 64 rows x 16 chunks
    const int drow = tid >> 3;                         // D: 128 rows x 16 chunks(2/thr)

    // group A = K(kt)+D(kt); group B = V(kt)
#define FILL_A(kt) {                                                            \
        __half* Ks = K2 + ((kt) & 1) * 64 * QSTR;                               \
        float*  Ds = D2 + ((kt) & 1) * 128 * DSTR;                              \
        cpa16(&Ks[frow * QSTR + fc8],                                           \
              &kbase[(size_t)((kt) * 64 + frow) * DH + fc8]);                   \
        _Pragma("unroll")                                                       \
        for (int t = 0; t < 2; t++) {                                           \
            int dc = ((tid & 7) + t * 8) * 4;                                   \
            cpa16(&Ds[drow * DSTR + dc],                                        \
                  &dbase[(size_t)drow * SEQ + (kt) * 64 + dc]);                 \
        }                                                                       \
        CP_COMMIT(); }
#define FILL_B(kt) {                                                            \
        __half* Vs = V2 + ((kt) & 1) * 64 * QSTR;                               \
        cpa16(&Vs[frow * QSTR + fc8],                                           \
              &vbase[(size_t)((kt) * 64 + frow) * DH + fc8]);                   \
        CP_COMMIT(); }

    // prologue: A(0) = [Q + K0 + D0], then B(0) = [V0]; Msa table
    {
#pragma unroll
        for (int t = 0; t < 2; t++) {
            int i = tid + t * 1024;
            int row = i >> 4, c8 = (i & 15) * 8;
            cpa16(&Qs[row * QSTR + c8], &qbase[(size_t)(q0 + row) * DH + c8]);
        }
        FILL_A(0);
        FILL_B(0);
        if (tid < 512) Msa[tid] = (mask[b * SEQ + tid] == 0.0f) ? -1e9f : 0.0f;
    }

    float O[4][4];
#pragma unroll
    for (int nf = 0; nf < 4; nf++)
#pragma unroll
        for (int i = 0; i < 4; i++) O[nf][i] = 0.0f;
    float l_t[2] = {0.0f, 0.0f};

    for (int kt = 0; kt < 8; kt++) {
        const __half* Ks = K2 + (kt & 1) * 64 * QSTR;
        const __half* Vs = V2 + (kt & 1) * 64 * QSTR;
        const float*  Ds = D2 + (kt & 1) * 128 * DSTR;
        const int k0 = kt * 64;
        CP_WAIT(1);                       // A(kt) done
        __syncthreads();                  // (also: everyone past PV(kt-1))

        // S init from dist tile + key mask, then S += Q @ K^T
        float s[2][4];
#pragma unroll
        for (int nf = 0; nf < 2; nf++) {
            int gcol = wn * 16 + nf * 8 + 2 * c;
            float2 d0 = *(const float2*)&Ds[(m0 + g) * DSTR + gcol];
            float2 d1 = *(const float2*)&Ds[(m0 + g + 8) * DSTR + gcol];
            float ma0 = Msa[k0 + gcol], ma1 = Msa[k0 + gcol + 1];
            s[nf][0] = d0.x + ma0; s[nf][1] = d0.y + ma1;
            s[nf][2] = d1.x + ma0; s[nf][3] = d1.y + ma1;
        }
#pragma unroll
        for (int kb = 0; kb < 8; kb++) {
            const int k16 = kb * 16 + 2 * c;
            unsigned a[4];
            a[0] = *(const unsigned*)&Qs[(m0 + g) * QSTR + k16];
            a[1] = *(const unsigned*)&Qs[(m0 + g + 8) * QSTR + k16];
            a[2] = *(const unsigned*)&Qs[(m0 + g) * QSTR + k16 + 8];
            a[3] = *(const unsigned*)&Qs[(m0 + g + 8) * QSTR + k16 + 8];
#pragma unroll
            for (int nf = 0; nf < 2; nf++) {
                int col = wn * 16 + nf * 8 + g;
                unsigned bfr[2];
                bfr[0] = *(const unsigned*)&Ks[col * QSTR + k16];
                bfr[1] = *(const unsigned*)&Ks[col * QSTR + k16 + 8];
                mma16(s[nf], a, bfr);
            }
        }
        if (kt < 7) FILL_A(kt + 1);       // other buffers; no barrier needed

        // softmax: p = exp(s)
#pragma unroll
        for (int rr = 0; rr < 2; rr++) {
            const int row = m0 + g + rr * 8;
#pragma unroll
            for (int nf = 0; nf < 2; nf++) {
                int gcol = wn * 16 + nf * 8 + 2 * c;
                float p0 = __expf(s[nf][rr * 2 + 0]);
                float p1 = __expf(s[nf][rr * 2 + 1]);
                l_t[rr] += p0 + p1;
                *(__half2*)&Ps[row * PSTR + gcol] = __floats2half2_rn(p0, p1);
            }
        }
        if (kt < 7) CP_WAIT(1); else CP_WAIT(0);   // B(kt) done
        __syncthreads();                  // Ps visible; Vs ready

        // O += P @ V : 16 rows x 32 D-cols, k = 64
#pragma unroll
        for (int ks = 0; ks < 4; ks++) {
            const int k16 = ks * 16;
            unsigned a[4];
            a[0] = *(const unsigned*)&Ps[(m0 + g) * PSTR + k16 + 2 * c];
            a[1] = *(const unsigned*)&Ps[(m0 + g + 8) * PSTR + k16 + 2 * c];
            a[2] = *(const unsigned*)&Ps[(m0 + g) * PSTR + k16 + 2 * c + 8];
            a[3] = *(const unsigned*)&Ps[(m0 + g + 8) * PSTR + k16 + 2 * c + 8];
#pragma unroll
            for (int nb = 0; nb < 2; nb++) {
                unsigned v[4];
                unsigned vaddr = smaddr(&Vs[(k16 + (lane & 15)) * QSTR +
                                            wn * 32 + nb * 16 + ((lane >> 4) << 3)]);
                ldsm4t(v, vaddr);
                mma16(O[nb * 2 + 0], a, v);
                mma16(O[nb * 2 + 1], a, v + 2);
            }
        }
        if (kt < 7) FILL_B(kt + 1);       // other buffer; no barrier needed
    }

    // l: reduce over quad lanes, then over 4 quarters via smem
#pragma unroll
    for (int rr = 0; rr < 2; rr++) {
        float lv = l_t[rr];
        lv += __shfl_xor_sync(0xffffffffu, lv, 1);
        lv += __shfl_xor_sync(0xffffffffu, lv, 2);
        if (c == 0) Lp[wn * 128 + m0 + g + rr * 8] = lv;
    }
    __syncthreads();

#pragma unroll
    for (int rr = 0; rr < 2; rr++) {
        int row = m0 + g + rr * 8;
        float l = Lp[row] + Lp[128 + row] + Lp[256 + row] + Lp[384 + row];
        float inv = (l > 0.0f) ? 1.0f / l : 0.0f;
        __half* orow = g_y1h + ((size_t)b * SEQ + q0 + row) * HD + h * DH + wn * 32;
#pragma unroll
        for (int nf = 0; nf < 4; nf++) {
            int col = nf * 8 + 2 * c;
            *(__half2*)&orow[col] =
                __floats2half2_rn(O[nf][rr * 2 + 0] * inv, O[nf][rr * 2 + 1] * inv);
        }
    }
}

// ---------------------------------------------------------------------------
// Output projection fp16: out = (y1 @ Wo + bo) * mask
// grid NROWS/32 = 256, 512 thr (16 warps: wm 0..1 x 16 rows, wn 0..7 x 16 cols)
// K staged 128 (8 stages), double-buf: As[32][136] + Bs(Wot)[128][136] / stage
// ---------------------------------------------------------------------------
#define OP_STG 21760
__global__ __launch_bounds__(512, 2) void oproj_kernel(
    const float* __restrict__ bo, const float* __restrict__ mask,
    float* __restrict__ out)
{
    extern __shared__ __half smh[];
    const int tid = threadIdx.x;
    const int wid = tid >> 5, lane = tid & 31;
    const int g = lane >> 2, c = lane & 3;
    const int wm = wid & 1, wn = wid >> 1;      // warp tile 16 x 16
    const int r0 = blockIdx.x * 32;
    const __half* abase = g_y1h + (size_t)r0 * HD;

    const int frow = tid >> 4, fc8 = (tid & 15) * 8;   // 32 rows x 16 chunks
#define OP_FILL(ks, buf) {                                                      \
        __half* As = smh + (buf) * OP_STG;                                      \
        __half* Bs = As + 4352;                                                 \
        const int k0 = (ks) * 128;                                              \
        cpa16(&As[frow * 136 + fc8], &abase[(size_t)frow * HD + k0 + fc8]);     \
        _Pragma("unroll")                                                       \
        for (int t = 0; t < 4; t++) {                                           \
            int row = frow + t * 32;                                            \
            cpa16(&Bs[row * 136 + fc8], &g_wot[(size_t)row * HD + k0 + fc8]);   \
        }                                                                       \
        CP_COMMIT(); }

    float acc[2][4];
#pragma unroll
    for (int nf = 0; nf < 2; nf++)
#pragma unroll
        for (int i = 0; i < 4; i++) acc[nf][i] = 0.0f;

    OP_FILL(0, 0);
    for (int ks = 0; ks < 8; ks++) {
        if (ks < 7) { OP_FILL(ks + 1, (ks + 1) & 1); CP_WAIT(1); }
        else        { CP_WAIT(0); }
        __syncthreads();
        const __half* As = smh + (ks & 1) * OP_STG;
        const __half* Bs = As + 4352;
#pragma unroll
        for (int kb = 0; kb < 8; kb++) {
            const int k16 = kb * 16 + 2 * c;
            unsigned a[4];
            int row = wm * 16;
            a[0] = *(const unsigned*)&As[(row + g) * 136 + k16];
            a[1] = *(const unsigned*)&As[(row + g + 8) * 136 + k16];
            a[2] = *(const unsigned*)&As[(row + g) * 136 + k16 + 8];
            a[3] = *(const unsigned*)&As[(row + g + 8) * 136 + k16 + 8];
#pragma unroll
            for (int nf = 0; nf < 2; nf++) {
                int col = wn * 16 + nf * 8;
                unsigned b[2];
                b[0] = *(const unsigned*)&Bs[(col + g) * 136 + k16];
                b[1] = *(const unsigned*)&Bs[(col + g) * 136 + k16 + 8];
                mma16(acc[nf], a, b);
            }
        }
        __syncthreads();
    }

#pragma unroll
    for (int rr = 0; rr < 2; rr++) {
        int row = r0 + wm * 16 + g + rr * 8;
        float mm = mask[row];
#pragma unroll
        for (int nf = 0; nf < 2; nf++) {
            int col = wn * 16 + nf * 8 + 2 * c;
            float v0 = (acc[nf][rr * 2 + 0] + bo[col]) * mm;
            float v1 = (acc[nf][rr * 2 + 1] + bo[col + 1]) * mm;
            *(float2*)&out[(size_t)row * DH + col] = make_float2(v0, v1);
        }
    }
}

// ---------------------------------------------------------------------------
extern "C" void kernel_launch(void* const* d_in, const int* in_sizes, int n_in,
                              void* d_out, int out_size)
{
    const float* x    = (const float*)d_in[0];
    const float* dist = (const float*)d_in[1];
    const float* mask = (const float*)d_in[2];
    const float* Wq   = (const float*)d_in[3];
    const float* bq   = (const float*)d_in[4];
    const float* Wk   = (const float*)d_in[5];
    const float* bk   = (const float*)d_in[6];
    const float* Wv   = (const float*)d_in[7];
    const float* bv   = (const float*)d_in[8];
    const float* Wo   = (const float*)d_in[9];
    const float* bo   = (const float*)d_in[10];
    float* out = (float*)d_out;

    const int proj_smem = PROJ_STG * 2 * 2;                            // 55296
    const int attn_smem = (17408 + 2*8704 + 2*8704 + 9216) * 2
                        + (2*128*DSTR + 512 + 512) * 4;                // 196608
    const int op_smem   = OP_STG * 2 * 2;                              // 87040
    static int configured = 0;
    if (!configured) {
        cudaFuncSetAttribute(proj_kernel, cudaFuncAttributeMaxDynamicSharedMemorySize, proj_smem);
        cudaFuncSetAttribute(attn_kernel, cudaFuncAttributeMaxDynamicSharedMemorySize, attn_smem);
        cudaFuncSetAttribute(oproj_kernel, cudaFuncAttributeMaxDynamicSharedMemorySize, op_smem);
        configured = 1;
    }

    prep_kernel<<<1024, 256>>>(x);
    wtrans_kernel<<<dim3(32, 32, 4), dim3(32, 8)>>>(Wq, Wk, Wv, Wo);
    proj_kernel<<<dim3(HD/64, NROWS/128, 3), 256, proj_smem>>>(mask, bq, bk, bv);
    attn_kernel<<<dim3(SEQ/128, BB*NH), 1024, attn_smem>>>(dist, mask);
    oproj_kernel<<<dim3(NROWS/32), 512, op_smem>>>(bo, mask, out);
}

// round 11
// speedup vs baseline: 1.0757x; 1.0757x over previous
#include <cuda_runtime.h>
#include <cuda_fp16.h>

#define BB   16
#define SEQ  512
#define NH   8
#define DH   128
#define HD   1024
#define NROWS (BB*SEQ)            // 8192
#define SCALE 0.08838834764831843f

// Scratch (no device allocation allowed)
__device__ __half g_q  [BB*NH*SEQ*DH]; // [B,H,N,D] masked*scaled fp16
__device__ __half g_k  [BB*NH*SEQ*DH]; // [B,H,N,D] masked fp16
__device__ __half g_v  [BB*NH*SEQ*DH]; // [B,H,N,D] masked fp16
__device__ __half g_dh [BB*SEQ*SEQ];   // dist + key-mask(-1e9), fp16
__device__ __half g_y1h[NROWS*HD];     // [B,N,H*D] attn out fp16
__device__ __half g_xh [NROWS*DH];     // x fp16
__device__ __half g_wqt[HD*DH];        // Wq^T [n][k] fp16
__device__ __half g_wkt[HD*DH];
__device__ __half g_wvt[HD*DH];
__device__ __half g_wot[DH*HD];        // Wo^T [n=128][k=1024] fp16

__device__ __forceinline__ void cpa16(void* dst_smem, const void* src_gmem) {
    unsigned s = (unsigned)__cvta_generic_to_shared(dst_smem);
    asm volatile("cp.async.cg.shared.global [%0], [%1], 16;\n" :: "r"(s), "l"(src_gmem));
}
#define CP_COMMIT() asm volatile("cp.async.commit_group;\n")
#define CP_WAIT(n)  asm volatile("cp.async.wait_group %0;\n" :: "n"(n))

// fp16 k16 mma, fp32 accum
__device__ __forceinline__ void mma16(float* d, const unsigned* a, const unsigned* b) {
    asm volatile(
        "mma.sync.aligned.m16n8k16.row.col.f32.f16.f16.f32 "
        "{%0,%1,%2,%3}, {%4,%5,%6,%7}, {%8,%9}, {%0,%1,%2,%3};"
        : "+f"(d[0]), "+f"(d[1]), "+f"(d[2]), "+f"(d[3])
        : "r"(a[0]), "r"(a[1]), "r"(a[2]), "r"(a[3]), "r"(b[0]), "r"(b[1]));
}
__device__ __forceinline__ unsigned smaddr(const void* p) {
    return (unsigned)__cvta_generic_to_shared(p);
}
__device__ __forceinline__ void ldsm4(unsigned* r, unsigned a) {
    asm volatile("ldmatrix.sync.aligned.m8n8.x4.shared.b16 {%0,%1,%2,%3}, [%4];"
        : "=r"(r[0]), "=r"(r[1]), "=r"(r[2]), "=r"(r[3]) : "r"(a));
}
__device__ __forceinline__ void ldsm4t(unsigned* r, unsigned a) {
    asm volatile("ldmatrix.sync.aligned.m8n8.x4.trans.shared.b16 {%0,%1,%2,%3}, [%4];"
        : "=r"(r[0]), "=r"(r[1]), "=r"(r[2]), "=r"(r[3]) : "r"(a));
}

// ---------------------------------------------------------------------------
// prep: x -> fp16. grid 1024 x 256
// ---------------------------------------------------------------------------
__global__ void prep_kernel(const float* __restrict__ x)
{
    int i = blockIdx.x * 256 + threadIdx.x;       // float4 index
    if (i < NROWS*DH/4) {
        float4 v = ((const float4*)x)[i];
        ((__half2*)g_xh)[i * 2 + 0] = __floats2half2_rn(v.x, v.y);
        ((__half2*)g_xh)[i * 2 + 1] = __floats2half2_rn(v.z, v.w);
    }
}

// ---------------------------------------------------------------------------
// weight transpose -> fp16: W[R=k][C=n] f32 -> Wt[C][R] h16. grid (32,32,4)
// ---------------------------------------------------------------------------
__global__ void wtrans_kernel(const float* __restrict__ Wq, const float* __restrict__ Wk,
                              const float* __restrict__ Wv, const float* __restrict__ Wo)
{
    __shared__ float t[32][33];
    const int z = blockIdx.z;
    const float* src = (z == 0) ? Wq : (z == 1) ? Wk : (z == 2) ? Wv : Wo;
    __half* dst = (z == 0) ? g_wqt : (z == 1) ? g_wkt : (z == 2) ? g_wvt : g_wot;
    const int R = (z < 3) ? DH : HD;
    const int C = (z < 3) ? HD : DH;
    if ((int)blockIdx.x * 32 >= C || (int)blockIdx.y * 32 >= R) return;
    const int tx = threadIdx.x, ty = threadIdx.y;
    const int r = blockIdx.y * 32, c = blockIdx.x * 32;
#pragma unroll
    for (int j = 0; j < 4; j++)
        t[ty + j*8][tx] = src[(size_t)(r + ty + j*8) * C + c + tx];
    __syncthreads();
#pragma unroll
    for (int j = 0; j < 4; j++)
        dst[(size_t)(c + ty + j*8) * R + r + tx] = __float2half_rn(t[tx][ty + j*8]);
}

// ---------------------------------------------------------------------------
// dprep: g_dh = fp16(dist + (mask[key]? 0 : -1e9)). grid 4096 x 256
// ---------------------------------------------------------------------------
__global__ void dprep_kernel(const float* __restrict__ dist,
                             const float* __restrict__ mask)
{
    size_t i4 = (size_t)blockIdx.x * 256 + threadIdx.x;
    float4 v = ((const float4*)dist)[i4];
    int m = (int)(i4 & 127) * 4;
    int b = (int)(i4 >> 16);
    const float* mrow = mask + b * SEQ;
    float a0 = v.x + ((mrow[m + 0] == 0.0f) ? -1e9f : 0.0f);
    float a1 = v.y + ((mrow[m + 1] == 0.0f) ? -1e9f : 0.0f);
    float a2 = v.z + ((mrow[m + 2] == 0.0f) ? -1e9f : 0.0f);
    float a3 = v.w + ((mrow[m + 3] == 0.0f) ? -1e9f : 0.0f);
    ((__half2*)g_dh)[i4 * 2 + 0] = __floats2half2_rn(a0, a1);
    ((__half2*)g_dh)[i4 * 2 + 1] = __floats2half2_rn(a2, a3);
}

// ---------------------------------------------------------------------------
// QKV projection fp16: out = (x @ W + b) * mask (* scale for q) -> fp16 [B,H,N,D]
// grid (HD/64, NROWS/128, 3), 256 thr; CTA tile 128x64, K staged 64, 4 CTAs/SM
// ---------------------------------------------------------------------------
#define PROJ_STG 13824
__global__ __launch_bounds__(256, 4) void proj_kernel(
    const float* __restrict__ mask,
    const float* __restrict__ bq, const float* __restrict__ bk,
    const float* __restrict__ bv)
{
    extern __shared__ __half smh[];
    const int tid = threadIdx.x;
    const int wid = tid >> 5, lane = tid & 31;
    const int g = lane >> 2, c = lane & 3;
    const int wm = wid & 3, wn = wid >> 2;       // warp tile 32 x 32
    const int c0 = blockIdx.x * 64;
    const int r0 = blockIdx.y * 128;
    const int sel = blockIdx.z;
    const __half* Wt  = (sel == 0) ? g_wqt : (sel == 1) ? g_wkt : g_wvt;
    const float* bias = (sel == 0) ? bq : (sel == 1) ? bk : bv;
    __half*      out  = (sel == 0) ? g_q : (sel == 1) ? g_k : g_v;
    const float extra = (sel == 0) ? SCALE : 1.0f;
    const __half* xbase = g_xh + (size_t)r0 * DH;
    const __half* wbase = Wt + (size_t)c0 * DH;

    const int frow = tid >> 3, fc8 = (tid & 7) * 8;
#define PROJ_FILL(ks, buf) {                                                    \
        __half* As = smh + (buf) * PROJ_STG;                                    \
        __half* Bs = As + 9216;                                                 \
        const int k0 = (ks) * 64;                                               \
        _Pragma("unroll")                                                       \
        for (int t = 0; t < 4; t++) {                                           \
            int row = frow + t * 32;                                            \
            cpa16(&As[row * 72 + fc8], &xbase[(size_t)row * DH + k0 + fc8]);    \
        }                                                                       \
        _Pragma("unroll")                                                       \
        for (int t = 0; t < 2; t++) {                                           \
            int row = frow + t * 32;                                            \
            cpa16(&Bs[row * 72 + fc8], &wbase[(size_t)row * DH + k0 + fc8]);    \
        }                                                                       \
        CP_COMMIT(); }

    float acc[2][4][4];
#pragma unroll
    for (int mf = 0; mf < 2; mf++)
#pragma unroll
        for (int nf = 0; nf < 4; nf++)
#pragma unroll
            for (int i = 0; i < 4; i++) acc[mf][nf][i] = 0.0f;

    PROJ_FILL(0, 0);
    for (int ks = 0; ks < 2; ks++) {
        if (ks < 1) { PROJ_FILL(1, 1); CP_WAIT(1); }
        else        { CP_WAIT(0); }
        __syncthreads();
        const __half* As = smh + (ks & 1) * PROJ_STG;
        const __half* Bs = As + 9216;
#pragma unroll
        for (int kb = 0; kb < 4; kb++) {
            const int k16 = kb * 16 + 2 * c;
            unsigned a[2][4];
#pragma unroll
            for (int mf = 0; mf < 2; mf++) {
                int row = wm * 32 + mf * 16;
                a[mf][0] = *(const unsigned*)&As[(row + g) * 72 + k16];
                a[mf][1] = *(const unsigned*)&As[(row + g + 8) * 72 + k16];
                a[mf][2] = *(const unsigned*)&As[(row + g) * 72 + k16 + 8];
                a[mf][3] = *(const unsigned*)&As[(row + g + 8) * 72 + k16 + 8];
            }
#pragma unroll
            for (int nf = 0; nf < 4; nf++) {
                int col = wn * 32 + nf * 8;
                unsigned b[2];
                b[0] = *(const unsigned*)&Bs[(col + g) * 72 + k16];
                b[1] = *(const unsigned*)&Bs[(col + g) * 72 + k16 + 8];
                mma16(acc[0][nf], a[0], b);
                mma16(acc[1][nf], a[1], b);
            }
        }
        __syncthreads();
    }

#pragma unroll
    for (int mf = 0; mf < 2; mf++) {
#pragma unroll
        for (int rr = 0; rr < 2; rr++) {
            int row = r0 + wm * 32 + mf * 16 + g + rr * 8;
            int bI = row >> 9, n = row & 511;
            float mm = mask[row] * extra;
#pragma unroll
            for (int nf = 0; nf < 4; nf++) {
                int col = c0 + wn * 32 + nf * 8 + 2 * c;
                int h = col >> 7, d = col & 127;
                float v0 = (acc[mf][nf][rr * 2 + 0] + bias[col]) * mm;
                float v1 = (acc[mf][nf][rr * 2 + 1] + bias[col + 1]) * mm;
                *(__half2*)&out[(((size_t)bI * NH + h) * SEQ + n) * DH + d] =
                    __floats2half2_rn(v0, v1);
            }
        }
    }
}

// ---------------------------------------------------------------------------
// Flash attention fp16, no-max softmax, K/V/D double-buffered (D = pre-fused
// fp16 dist+mask), ldmatrix fragment loads for Q/K/P, ldsm.trans for V.
// grid (SEQ/128, BB*NH), 1024 thr (32 warps: 8 row-groups x 4 quarters).
// smem (halves): Qs[128][136] K2[2][64][136] V2[2][64][136] D2[2][128][72]
//                Ps[128][72] + float Lp[512]  => 161792 B
// ---------------------------------------------------------------------------
#define QSTR 136
#define PSTR 72
__global__ __launch_bounds__(1024, 1) void attn_kernel()
{
    extern __shared__ __half smh[];
    __half* Qs = smh;                    // 17408 h
    __half* K2 = Qs + 128 * QSTR;        // 2 x 8704 h
    __half* V2 = K2 + 2 * 64 * QSTR;     // 2 x 8704 h
    __half* D2 = V2 + 2 * 64 * QSTR;     // 2 x 9216 h
    __half* Ps = D2 + 2 * 128 * PSTR;    // 9216 h
    float*  Lp = (float*)(Ps + 128 * PSTR);  // 512 f

    const int tid = threadIdx.x;
    const int wid = tid >> 5, lane = tid & 31;
    const int g = lane >> 2, c = lane & 3;
    const int wm = wid & 7, wn = wid >> 3;   // 8 row-groups x 4 quarters
    const int bh = blockIdx.y;
    const int b = bh >> 3, h = bh & 7;
    const int q0 = blockIdx.x * 128;
    const int m0 = wm * 16;

    // ldmatrix lane-coords
    const int arow = m0 + (lane & 7) + (((lane >> 3) & 1) << 3);  // A-frag row
    const int akoff = (lane >> 4) << 3;                           // A-frag k off
    const int bcol = wn * 16 + (lane & 7) + ((lane >> 4) << 3);   // B-frag col
    const int bkoff = ((lane >> 3) & 1) << 3;                     // B-frag k off

    const __half* qbase = g_q + (size_t)bh * SEQ * DH;
    const __half* kbase = g_k + (size_t)bh * SEQ * DH;
    const __half* vbase = g_v + (size_t)bh * SEQ * DH;
    const __half* dbase = g_dh + ((size_t)b * SEQ + q0) * SEQ;

    const int frow = tid >> 4, fc8 = (tid & 15) * 8;   // K/V: 64 rows x 16 chunks
    const int drow = tid >> 3, dc8 = (tid & 7) * 8;    // D: 128 rows x 8 chunks

#define FILL_A(kt) {                                                            \
        __half* Ks = K2 + ((kt) & 1) * 64 * QSTR;                               \
        __half* Ds = D2 + ((kt) & 1) * 128 * PSTR;                              \
        cpa16(&Ks[frow * QSTR + fc8],                                           \
              &kbase[(size_t)((kt) * 64 + frow) * DH + fc8]);                   \
        cpa16(&Ds[drow * PSTR + dc8],                                           \
              &dbase[(size_t)drow * SEQ + (kt) * 64 + dc8]);                    \
        CP_COMMIT(); }
#define FILL_B(kt) {                                                            \
        __half* Vs = V2 + ((kt) & 1) * 64 * QSTR;                               \
        cpa16(&Vs[frow * QSTR + fc8],                                           \
              &vbase[(size_t)((kt) * 64 + frow) * DH + fc8]);                   \
        CP_COMMIT(); }

    // prologue: A(0) = [Q + K0 + D0], then B(0) = [V0]
    {
#pragma unroll
        for (int t = 0; t < 2; t++) {
            int i = tid + t * 1024;
            int row = i >> 4, c8 = (i & 15) * 8;
            cpa16(&Qs[row * QSTR + c8], &qbase[(size_t)(q0 + row) * DH + c8]);
        }
        cpa16(&K2[frow * QSTR + fc8], &kbase[(size_t)frow * DH + fc8]);
        cpa16(&D2[drow * PSTR + dc8], &dbase[(size_t)drow * SEQ + dc8]);
        CP_COMMIT();
        FILL_B(0);
    }

    float O[4][4];
#pragma unroll
    for (int nf = 0; nf < 4; nf++)
#pragma unroll
        for (int i = 0; i < 4; i++) O[nf][i] = 0.0f;
    float l_t[2] = {0.0f, 0.0f};

    const unsigned aQ = smaddr(&Qs[arow * QSTR + akoff]);
    const unsigned aP = smaddr(&Ps[arow * PSTR + akoff]);

    for (int kt = 0; kt < 8; kt++) {
        const __half* Ks = K2 + (kt & 1) * 64 * QSTR;
        const __half* Vs = V2 + (kt & 1) * 64 * QSTR;
        const __half* Ds = D2 + (kt & 1) * 128 * PSTR;
        const unsigned bK = smaddr(Ks) + (bcol * QSTR + bkoff) * 2;
        CP_WAIT(1);                       // A(kt) done
        __syncthreads();                  // everyone past PV(kt-1)

        // S init from dist tile (dist+mask pre-fused), then S += Q @ K^T
        float s[2][4];
#pragma unroll
        for (int nf = 0; nf < 2; nf++) {
            int gcol = wn * 16 + nf * 8 + 2 * c;
            float2 d0 = __half22float2(*(const __half2*)&Ds[(m0 + g) * PSTR + gcol]);
            float2 d1 = __half22float2(*(const __half2*)&Ds[(m0 + g + 8) * PSTR + gcol]);
            s[nf][0] = d0.x; s[nf][1] = d0.y;
            s[nf][2] = d1.x; s[nf][3] = d1.y;
        }
#pragma unroll
        for (int kb = 0; kb < 8; kb++) {
            unsigned a[4], bk_[4];
            ldsm4(a, aQ + kb * 32);
            ldsm4(bk_, bK + kb * 32);
            mma16(s[0], a, bk_);
            mma16(s[1], a, bk_ + 2);
        }
        if (kt < 7) FILL_A(kt + 1);       // other buffers; no barrier needed

        // softmax: p = exp(s)
#pragma unroll
        for (int rr = 0; rr < 2; rr++) {
            const int row = m0 + g + rr * 8;
#pragma unroll
            for (int nf = 0; nf < 2; nf++) {
                int gcol = wn * 16 + nf * 8 + 2 * c;
                float p0 = __expf(s[nf][rr * 2 + 0]);
                float p1 = __expf(s[nf][rr * 2 + 1]);
                l_t[rr] += p0 + p1;
                *(__half2*)&Ps[row * PSTR + gcol] = __floats2half2_rn(p0, p1);
            }
        }
        if (kt < 7) CP_WAIT(1); else CP_WAIT(0);   // B(kt) done
        __syncthreads();                  // Ps visible; Vs ready

        // O += P @ V : 16 rows x 32 D-cols, k = 64
#pragma unroll
        for (int ks = 0; ks < 4; ks++) {
            unsigned a[4];
            ldsm4(a, aP + ks * 32);
#pragma unroll
            for (int nb = 0; nb < 2; nb++) {
                unsigned v[4];
                unsigned vaddr = smaddr(&Vs[(ks * 16 + (lane & 15)) * QSTR +
                                            wn * 32 + nb * 16 + ((lane >> 4) << 3)]);
                ldsm4t(v, vaddr);
                mma16(O[nb * 2 + 0], a, v);
                mma16(O[nb * 2 + 1], a, v + 2);
            }
        }
        if (kt < 7) FILL_B(kt + 1);       // other buffer; no barrier needed
    }

    // l: reduce over quad lanes, then over 4 quarters via smem
#pragma unroll
    for (int rr = 0; rr < 2; rr++) {
        float lv = l_t[rr];
        lv += __shfl_xor_sync(0xffffffffu, lv, 1);
        lv += __shfl_xor_sync(0xffffffffu, lv, 2);
        if (c == 0) Lp[wn * 128 + m0 + g + rr * 8] = lv;
    }
    __syncthreads();

#pragma unroll
    for (int rr = 0; rr < 2; rr++) {
        int row = m0 + g + rr * 8;
        float l = Lp[row] + Lp[128 + row] + Lp[256 + row] + Lp[384 + row];
        float inv = (l > 0.0f) ? 1.0f / l : 0.0f;
        __half* orow = g_y1h + ((size_t)b * SEQ + q0 + row) * HD + h * DH + wn * 32;
#pragma unroll
        for (int nf = 0; nf < 4; nf++) {
            int col = nf * 8 + 2 * c;
            *(__half2*)&orow[col] =
                __floats2half2_rn(O[nf][rr * 2 + 0] * inv, O[nf][rr * 2 + 1] * inv);
        }
    }
}

// ---------------------------------------------------------------------------
// Output projection fp16: out = (y1 @ Wo + bo) * mask
// grid NROWS/32 = 256, 512 thr (16 warps: wm 0..1 x 16 rows, wn 0..7 x 16 cols)
// K staged 128 (8 stages), double-buf
// ---------------------------------------------------------------------------
#define OP_STG 21760
__global__ __launch_bounds__(512, 2) void oproj_kernel(
    const float* __restrict__ bo, const float* __restrict__ mask,
    float* __restrict__ out)
{
    extern __shared__ __half smh[];
    const int tid = threadIdx.x;
    const int wid = tid >> 5, lane = tid & 31;
    const int g = lane >> 2, c = lane & 3;
    const int wm = wid & 1, wn = wid >> 1;      // warp tile 16 x 16
    const int r0 = blockIdx.x * 32;
    const __half* abase = g_y1h + (size_t)r0 * HD;

    const int frow = tid >> 4, fc8 = (tid & 15) * 8;
#define OP_FILL(ks, buf) {                                                      \
        __half* As = smh + (buf) * OP_STG;                                      \
        __half* Bs = As + 4352;                                                 \
        const int k0 = (ks) * 128;                                              \
        cpa16(&As[frow * 136 + fc8], &abase[(size_t)frow * HD + k0 + fc8]);     \
        _Pragma("unroll")                                                       \
        for (int t = 0; t < 4; t++) {                                           \
            int row = frow + t * 32;                                            \
            cpa16(&Bs[row * 136 + fc8], &g_wot[(size_t)row * HD + k0 + fc8]);   \
        }                                                                       \
        CP_COMMIT(); }

    float acc[2][4];
#pragma unroll
    for (int nf = 0; nf < 2; nf++)
#pragma unroll
        for (int i = 0; i < 4; i++) acc[nf][i] = 0.0f;

    OP_FILL(0, 0);
    for (int ks = 0; ks < 8; ks++) {
        if (ks < 7) { OP_FILL(ks + 1, (ks + 1) & 1); CP_WAIT(1); }
        else        { CP_WAIT(0); }
        __syncthreads();
        const __half* As = smh + (ks & 1) * OP_STG;
        const __half* Bs = As + 4352;
#pragma unroll
        for (int kb = 0; kb < 8; kb++) {
            const int k16 = kb * 16 + 2 * c;
            unsigned a[4];
            int row = wm * 16;
            a[0] = *(const unsigned*)&As[(row + g) * 136 + k16];
            a[1] = *(const unsigned*)&As[(row + g + 8) * 136 + k16];
            a[2] = *(const unsigned*)&As[(row + g) * 136 + k16 + 8];
            a[3] = *(const unsigned*)&As[(row + g + 8) * 136 + k16 + 8];
#pragma unroll
            for (int nf = 0; nf < 2; nf++) {
                int col = wn * 16 + nf * 8;
                unsigned b[2];
                b[0] = *(const unsigned*)&Bs[(col + g) * 136 + k16];
                b[1] = *(const unsigned*)&Bs[(col + g) * 136 + k16 + 8];
                mma16(acc[nf], a, b);
            }
        }
        __syncthreads();
    }

#pragma unroll
    for (int rr = 0; rr < 2; rr++) {
        int row = r0 + wm * 16 + g + rr * 8;
        float mm = mask[row];
#pragma unroll
        for (int nf = 0; nf < 2; nf++) {
            int col = wn * 16 + nf * 8 + 2 * c;
            float v0 = (acc[nf][rr * 2 + 0] + bo[col]) * mm;
            float v1 = (acc[nf][rr * 2 + 1] + bo[col + 1]) * mm;
            *(float2*)&out[(size_t)row * DH + col] = make_float2(v0, v1);
        }
    }
}

// ---------------------------------------------------------------------------
extern "C" void kernel_launch(void* const* d_in, const int* in_sizes, int n_in,
                              void* d_out, int out_size)
{
    const float* x    = (const float*)d_in[0];
    const float* dist = (const float*)d_in[1];
    const float* mask = (const float*)d_in[2];
    const float* Wq   = (const float*)d_in[3];
    const float* bq   = (const float*)d_in[4];
    const float* Wk   = (const float*)d_in[5];
    const float* bk   = (const float*)d_in[6];
    const float* Wv   = (const float*)d_in[7];
    const float* bv   = (const float*)d_in[8];
    const float* Wo   = (const float*)d_in[9];
    const float* bo   = (const float*)d_in[10];
    float* out = (float*)d_out;

    const int proj_smem = PROJ_STG * 2 * 2;                            // 55296
    const int attn_smem = (17408 + 2*8704 + 2*8704 + 2*9216 + 9216) * 2 + 512 * 4; // 161792
    const int op_smem   = OP_STG * 2 * 2;                              // 87040
    static int configured = 0;
    if (!configured) {
        cudaFuncSetAttribute(proj_kernel, cudaFuncAttributeMaxDynamicSharedMemorySize, proj_smem);
        cudaFuncSetAttribute(attn_kernel, cudaFuncAttributeMaxDynamicSharedMemorySize, attn_smem);
        cudaFuncSetAttribute(oproj_kernel, cudaFuncAttributeMaxDynamicSharedMemorySize, op_smem);
        configured = 1;
    }

    prep_kernel<<<1024, 256>>>(x);
    wtrans_kernel<<<dim3(32, 32, 4), dim3(32, 8)>>>(Wq, Wk, Wv, Wo);
    dprep_kernel<<<4096, 256>>>(dist, mask);
    proj_kernel<<<dim3(HD/64, NROWS/128, 3), 256, proj_smem>>>(mask, bq, bk, bv);
    attn_kernel<<<dim3(SEQ/128, BB*NH), 1024, attn_smem>>>();
    oproj_kernel<<<dim3(NROWS/32), 512, op_smem>>>(bo, mask, out);
}

// round 12
// speedup vs baseline: 1.0773x; 1.0016x over previous
#include <cuda_runtime.h>
#include <cuda_fp16.h>

#define BB   16
#define SEQ  512
#define NH   8
#define DH   128
#define HD   1024
#define NROWS (BB*SEQ)            // 8192
#define SCALE 0.08838834764831843f

// Scratch (no device allocation allowed)
__device__ __half g_q  [BB*NH*SEQ*DH]; // [B,H,N,D] masked*scaled fp16
__device__ __half g_k  [BB*NH*SEQ*DH]; // [B,H,N,D] masked fp16
__device__ __half g_v  [BB*NH*SEQ*DH]; // [B,H,N,D] masked fp16
__device__ __half g_dh [BB*SEQ*SEQ];   // dist + key-mask(-1e9), fp16
__device__ __half g_y1h[NROWS*HD];     // [B,N,H*D] attn out fp16
__device__ __half g_xh [NROWS*DH];     // x fp16
__device__ __half g_wqt[HD*DH];        // Wq^T [n][k] fp16
__device__ __half g_wkt[HD*DH];
__device__ __half g_wvt[HD*DH];
__device__ __half g_wot[DH*HD];        // Wo^T [n=128][k=1024] fp16

__device__ __forceinline__ void cpa16(void* dst_smem, const void* src_gmem) {
    unsigned s = (unsigned)__cvta_generic_to_shared(dst_smem);
    asm volatile("cp.async.cg.shared.global [%0], [%1], 16;\n" :: "r"(s), "l"(src_gmem));
}
#define CP_COMMIT() asm volatile("cp.async.commit_group;\n")
#define CP_WAIT(n)  asm volatile("cp.async.wait_group %0;\n" :: "n"(n))

// fp16 k16 mma, fp32 accum
__device__ __forceinline__ void mma16(float* d, const unsigned* a, const unsigned* b) {
    asm volatile(
        "mma.sync.aligned.m16n8k16.row.col.f32.f16.f16.f32 "
        "{%0,%1,%2,%3}, {%4,%5,%6,%7}, {%8,%9}, {%0,%1,%2,%3};"
        : "+f"(d[0]), "+f"(d[1]), "+f"(d[2]), "+f"(d[3])
        : "r"(a[0]), "r"(a[1]), "r"(a[2]), "r"(a[3]), "r"(b[0]), "r"(b[1]));
}
__device__ __forceinline__ unsigned smaddr(const void* p) {
    return (unsigned)__cvta_generic_to_shared(p);
}
__device__ __forceinline__ void ldsm4(unsigned* r, unsigned a) {
    asm volatile("ldmatrix.sync.aligned.m8n8.x4.shared.b16 {%0,%1,%2,%3}, [%4];"
        : "=r"(r[0]), "=r"(r[1]), "=r"(r[2]), "=r"(r[3]) : "r"(a));
}
__device__ __forceinline__ void ldsm4t(unsigned* r, unsigned a) {
    asm volatile("ldmatrix.sync.aligned.m8n8.x4.trans.shared.b16 {%0,%1,%2,%3}, [%4];"
        : "=r"(r[0]), "=r"(r[1]), "=r"(r[2]), "=r"(r[3]) : "r"(a));
}

// ---------------------------------------------------------------------------
// prep: x -> fp16. grid 1024 x 256
// ---------------------------------------------------------------------------
__global__ void prep_kernel(const float* __restrict__ x)
{
    int i = blockIdx.x * 256 + threadIdx.x;       // float4 index
    if (i < NROWS*DH/4) {
        float4 v = ((const float4*)x)[i];
        ((__half2*)g_xh)[i * 2 + 0] = __floats2half2_rn(v.x, v.y);
        ((__half2*)g_xh)[i * 2 + 1] = __floats2half2_rn(v.z, v.w);
    }
}

// ---------------------------------------------------------------------------
// weight transpose -> fp16: W[R=k][C=n] f32 -> Wt[C][R] h16. grid (32,32,4)
// ---------------------------------------------------------------------------
__global__ void wtrans_kernel(const float* __restrict__ Wq, const float* __restrict__ Wk,
                              const float* __restrict__ Wv, const float* __restrict__ Wo)
{
    __shared__ float t[32][33];
    const int z = blockIdx.z;
    const float* src = (z == 0) ? Wq : (z == 1) ? Wk : (z == 2) ? Wv : Wo;
    __half* dst = (z == 0) ? g_wqt : (z == 1) ? g_wkt : (z == 2) ? g_wvt : g_wot;
    const int R = (z < 3) ? DH : HD;
    const int C = (z < 3) ? HD : DH;
    if ((int)blockIdx.x * 32 >= C || (int)blockIdx.y * 32 >= R) return;
    const int tx = threadIdx.x, ty = threadIdx.y;
    const int r = blockIdx.y * 32, c = blockIdx.x * 32;
#pragma unroll
    for (int j = 0; j < 4; j++)
        t[ty + j*8][tx] = src[(size_t)(r + ty + j*8) * C + c + tx];
    __syncthreads();
#pragma unroll
    for (int j = 0; j < 4; j++)
        dst[(size_t)(c + ty + j*8) * R + r + tx] = __float2half_rn(t[tx][ty + j*8]);
}

// ---------------------------------------------------------------------------
// dprep: g_dh = fp16(dist + (mask[key]? 0 : -1e9)). grid 4096 x 256
// ---------------------------------------------------------------------------
__global__ void dprep_kernel(const float* __restrict__ dist,
                             const float* __restrict__ mask)
{
    size_t i4 = (size_t)blockIdx.x * 256 + threadIdx.x;
    float4 v = ((const float4*)dist)[i4];
    int m = (int)(i4 & 127) * 4;
    int b = (int)(i4 >> 16);
    const float* mrow = mask + b * SEQ;
    float a0 = v.x + ((mrow[m + 0] == 0.0f) ? -1e9f : 0.0f);
    float a1 = v.y + ((mrow[m + 1] == 0.0f) ? -1e9f : 0.0f);
    float a2 = v.z + ((mrow[m + 2] == 0.0f) ? -1e9f : 0.0f);
    float a3 = v.w + ((mrow[m + 3] == 0.0f) ? -1e9f : 0.0f);
    ((__half2*)g_dh)[i4 * 2 + 0] = __floats2half2_rn(a0, a1);
    ((__half2*)g_dh)[i4 * 2 + 1] = __floats2half2_rn(a2, a3);
}

// ---------------------------------------------------------------------------
// QKV projection fp16, SINGLE-STAGE K=128:
// out = (x @ W + b) * mask (* scale for q) -> fp16 [B,H,N,D]
// grid (HD/64, NROWS/128, 3), 256 thr (8 warps: wm 0..3 x 32 rows, wn 0..1 x
// 32 cols); smem: As[128][136] + Bs[64][136] = 26112 h = 52224 B, 4 CTAs/SM
// ---------------------------------------------------------------------------
#define PRSTR 136
__global__ __launch_bounds__(256, 4) void proj_kernel(
    const float* __restrict__ mask,
    const float* __restrict__ bq, const float* __restrict__ bk,
    const float* __restrict__ bv)
{
    extern __shared__ __half smh[];
    __half* As = smh;                 // [128][136]
    __half* Bs = As + 128 * PRSTR;    // [64][136]
    const int tid = threadIdx.x;
    const int wid = tid >> 5, lane = tid & 31;
    const int g = lane >> 2, c = lane & 3;
    const int wm = wid & 3, wn = wid >> 2;       // warp tile 32 x 32
    const int c0 = blockIdx.x * 64;
    const int r0 = blockIdx.y * 128;
    const int sel = blockIdx.z;
    const __half* Wt  = (sel == 0) ? g_wqt : (sel == 1) ? g_wkt : g_wvt;
    const float* bias = (sel == 0) ? bq : (sel == 1) ? bk : bv;
    __half*      out  = (sel == 0) ? g_q : (sel == 1) ? g_k : g_v;
    const float extra = (sel == 0) ? SCALE : 1.0f;
    const __half* xbase = g_xh + (size_t)r0 * DH;
    const __half* wbase = Wt + (size_t)c0 * DH;

    // fill: whole K=128 in one pass. 16 rows x 16 chunks per 256 threads.
    const int frow = tid >> 4, fc8 = (tid & 15) * 8;
#pragma unroll
    for (int t = 0; t < 8; t++) {
        int row = frow + t * 16;
        cpa16(&As[row * PRSTR + fc8], &xbase[(size_t)row * DH + fc8]);
    }
#pragma unroll
    for (int t = 0; t < 4; t++) {
        int row = frow + t * 16;
        cpa16(&Bs[row * PRSTR + fc8], &wbase[(size_t)row * DH + fc8]);
    }
    CP_COMMIT();

    float acc[2][4][4];
#pragma unroll
    for (int mf = 0; mf < 2; mf++)
#pragma unroll
        for (int nf = 0; nf < 4; nf++)
#pragma unroll
            for (int i = 0; i < 4; i++) acc[mf][nf][i] = 0.0f;

    CP_WAIT(0);
    __syncthreads();

#pragma unroll
    for (int kb = 0; kb < 8; kb++) {
        const int k16 = kb * 16 + 2 * c;
        unsigned a[2][4];
#pragma unroll
        for (int mf = 0; mf < 2; mf++) {
            int row = wm * 32 + mf * 16;
            a[mf][0] = *(const unsigned*)&As[(row + g) * PRSTR + k16];
            a[mf][1] = *(const unsigned*)&As[(row + g + 8) * PRSTR + k16];
            a[mf][2] = *(const unsigned*)&As[(row + g) * PRSTR + k16 + 8];
            a[mf][3] = *(const unsigned*)&As[(row + g + 8) * PRSTR + k16 + 8];
        }
#pragma unroll
        for (int nf = 0; nf < 4; nf++) {
            int col = wn * 32 + nf * 8;
            unsigned b[2];
            b[0] = *(const unsigned*)&Bs[(col + g) * PRSTR + k16];
            b[1] = *(const unsigned*)&Bs[(col + g) * PRSTR + k16 + 8];
            mma16(acc[0][nf], a[0], b);
            mma16(acc[1][nf], a[1], b);
        }
    }

#pragma unroll
    for (int mf = 0; mf < 2; mf++) {
#pragma unroll
        for (int rr = 0; rr < 2; rr++) {
            int row = r0 + wm * 32 + mf * 16 + g + rr * 8;
            int bI = row >> 9, n = row & 511;
            float mm = mask[row] * extra;
#pragma unroll
            for (int nf = 0; nf < 4; nf++) {
                int col = c0 + wn * 32 + nf * 8 + 2 * c;
                int h = col >> 7, d = col & 127;
                float v0 = (acc[mf][nf][rr * 2 + 0] + bias[col]) * mm;
                float v1 = (acc[mf][nf][rr * 2 + 1] + bias[col + 1]) * mm;
                *(__half2*)&out[(((size_t)bI * NH + h) * SEQ + n) * DH + d] =
                    __floats2half2_rn(v0, v1);
            }
        }
    }
}

// ---------------------------------------------------------------------------
// Flash attention fp16, no-max softmax, K/V/D double-buffered (D = pre-fused
// fp16 dist+mask), ldmatrix fragment loads for Q/K/P, ldsm.trans for V.
// grid (SEQ/128, BB*NH), 1024 thr (32 warps: 8 row-groups x 4 quarters).
// smem (halves): Qs[128][136] K2[2][64][136] V2[2][64][136] D2[2][128][72]
//                Ps[128][72] + float Lp[512]  => 161792 B
// ---------------------------------------------------------------------------
#define QSTR 136
#define PSTR 72
__global__ __launch_bounds__(1024, 1) void attn_kernel()
{
    extern __shared__ __half smh[];
    __half* Qs = smh;                    // 17408 h
    __half* K2 = Qs + 128 * QSTR;        // 2 x 8704 h
    __half* V2 = K2 + 2 * 64 * QSTR;     // 2 x 8704 h
    __half* D2 = V2 + 2 * 64 * QSTR;     // 2 x 9216 h
    __half* Ps = D2 + 2 * 128 * PSTR;    // 9216 h
    float*  Lp = (float*)(Ps + 128 * PSTR);  // 512 f

    const int tid = threadIdx.x;
    const int wid = tid >> 5, lane = tid & 31;
    const int g = lane >> 2, c = lane & 3;
    const int wm = wid & 7, wn = wid >> 3;   // 8 row-groups x 4 quarters
    const int bh = blockIdx.y;
    const int b = bh >> 3, h = bh & 7;
    const int q0 = blockIdx.x * 128;
    const int m0 = wm * 16;

    // ldmatrix lane-coords
    const int arow = m0 + (lane & 7) + (((lane >> 3) & 1) << 3);  // A-frag row
    const int akoff = (lane >> 4) << 3;                           // A-frag k off
    const int bcol = wn * 16 + (lane & 7) + ((lane >> 4) << 3);   // B-frag col
    const int bkoff = ((lane >> 3) & 1) << 3;                     // B-frag k off

    const __half* qbase = g_q + (size_t)bh * SEQ * DH;
    const __half* kbase = g_k + (size_t)bh * SEQ * DH;
    const __half* vbase = g_v + (size_t)bh * SEQ * DH;
    const __half* dbase = g_dh + ((size_t)b * SEQ + q0) * SEQ;

    const int frow = tid >> 4, fc8 = (tid & 15) * 8;   // K/V: 64 rows x 16 chunks
    const int drow = tid >> 3, dc8 = (tid & 7) * 8;    // D: 128 rows x 8 chunks

#define FILL_A(kt) {                                                            \
        __half* Ks = K2 + ((kt) & 1) * 64 * QSTR;                               \
        __half* Ds = D2 + ((kt) & 1) * 128 * PSTR;                              \
        cpa16(&Ks[frow * QSTR + fc8],                                           \
              &kbase[(size_t)((kt) * 64 + frow) * DH + fc8]);                   \
        cpa16(&Ds[drow * PSTR + dc8],                                           \
              &dbase[(size_t)drow * SEQ + (kt) * 64 + dc8]);                    \
        CP_COMMIT(); }
#define FILL_B(kt) {                                                            \
        __half* Vs = V2 + ((kt) & 1) * 64 * QSTR;                               \
        cpa16(&Vs[frow * QSTR + fc8],                                           \
              &vbase[(size_t)((kt) * 64 + frow) * DH + fc8]);                   \
        CP_COMMIT(); }

    // prologue: A(0) = [Q + K0 + D0], then B(0) = [V0]
    {
#pragma unroll
        for (int t = 0; t < 2; t++) {
            int i = tid + t * 1024;
            int row = i >> 4, c8 = (i & 15) * 8;
            cpa16(&Qs[row * QSTR + c8], &qbase[(size_t)(q0 + row) * DH + c8]);
        }
        cpa16(&K2[frow * QSTR + fc8], &kbase[(size_t)frow * DH + fc8]);
        cpa16(&D2[drow * PSTR + dc8], &dbase[(size_t)drow * SEQ + dc8]);
        CP_COMMIT();
        FILL_B(0);
    }

    float O[4][4];
#pragma unroll
    for (int nf = 0; nf < 4; nf++)
#pragma unroll
        for (int i = 0; i < 4; i++) O[nf][i] = 0.0f;
    float l_t[2] = {0.0f, 0.0f};

    const unsigned aQ = smaddr(&Qs[arow * QSTR + akoff]);
    const unsigned aP = smaddr(&Ps[arow * PSTR + akoff]);

    for (int kt = 0; kt < 8; kt++) {
        const __half* Ks = K2 + (kt & 1) * 64 * QSTR;
        const __half* Vs = V2 + (kt & 1) * 64 * QSTR;
        const __half* Ds = D2 + (kt & 1) * 128 * PSTR;
        const unsigned bK = smaddr(Ks) + (bcol * QSTR + bkoff) * 2;
        CP_WAIT(1);                       // A(kt) done
        __syncthreads();                  // everyone past PV(kt-1)

        // S init from dist tile (dist+mask pre-fused), then S += Q @ K^T
        float s[2][4];
#pragma unroll
        for (int nf = 0; nf < 2; nf++) {
            int gcol = wn * 16 + nf * 8 + 2 * c;
            float2 d0 = __half22float2(*(const __half2*)&Ds[(m0 + g) * PSTR + gcol]);
            float2 d1 = __half22float2(*(const __half2*)&Ds[(m0 + g + 8) * PSTR + gcol]);
            s[nf][0] = d0.x; s[nf][1] = d0.y;
            s[nf][2] = d1.x; s[nf][3] = d1.y;
        }
#pragma unroll
        for (int kb = 0; kb < 8; kb++) {
            unsigned a[4], bk_[4];
            ldsm4(a, aQ + kb * 32);
            ldsm4(bk_, bK + kb * 32);
            mma16(s[0], a, bk_);
            mma16(s[1], a, bk_ + 2);
        }
        if (kt < 7) FILL_A(kt + 1);       // other buffers; no barrier needed

        // softmax: p = exp(s)
#pragma unroll
        for (int rr = 0; rr < 2; rr++) {
            const int row = m0 + g + rr * 8;
#pragma unroll
            for (int nf = 0; nf < 2; nf++) {
                int gcol = wn * 16 + nf * 8 + 2 * c;
                float p0 = __expf(s[nf][rr * 2 + 0]);
                float p1 = __expf(s[nf][rr * 2 + 1]);
                l_t[rr] += p0 + p1;
                *(__half2*)&Ps[row * PSTR + gcol] = __floats2half2_rn(p0, p1);
            }
        }
        if (kt < 7) CP_WAIT(1); else CP_WAIT(0);   // B(kt) done
        __syncthreads();                  // Ps visible; Vs ready

        // O += P @ V : 16 rows x 32 D-cols, k = 64
#pragma unroll
        for (int ks = 0; ks < 4; ks++) {
            unsigned a[4];
            ldsm4(a, aP + ks * 32);
#pragma unroll
            for (int nb = 0; nb < 2; nb++) {
                unsigned v[4];
                unsigned vaddr = smaddr(&Vs[(ks * 16 + (lane & 15)) * QSTR +
                                            wn * 32 + nb * 16 + ((lane >> 4) << 3)]);
                ldsm4t(v, vaddr);
                mma16(O[nb * 2 + 0], a, v);
                mma16(O[nb * 2 + 1], a, v + 2);
            }
        }
        if (kt < 7) FILL_B(kt + 1);       // other buffer; no barrier needed
    }

    // l: reduce over quad lanes, then over 4 quarters via smem
#pragma unroll
    for (int rr = 0; rr < 2; rr++) {
        float lv = l_t[rr];
        lv += __shfl_xor_sync(0xffffffffu, lv, 1);
        lv += __shfl_xor_sync(0xffffffffu, lv, 2);
        if (c == 0) Lp[wn * 128 + m0 + g + rr * 8] = lv;
    }
    __syncthreads();

#pragma unroll
    for (int rr = 0; rr < 2; rr++) {
        int row = m0 + g + rr * 8;
        float l = Lp[row] + Lp[128 + row] + Lp[256 + row] + Lp[384 + row];
        float inv = (l > 0.0f) ? 1.0f / l : 0.0f;
        __half* orow = g_y1h + ((size_t)b * SEQ + q0 + row) * HD + h * DH + wn * 32;
#pragma unroll
        for (int nf = 0; nf < 4; nf++) {
            int col = nf * 8 + 2 * c;
            *(__half2*)&orow[col] =
                __floats2half2_rn(O[nf][rr * 2 + 0] * inv, O[nf][rr * 2 + 1] * inv);
        }
    }
}

// ---------------------------------------------------------------------------
// Output projection fp16: out = (y1 @ Wo + bo) * mask
// grid NROWS/32 = 256, 512 thr (16 warps: wm 0..1 x 16 rows, wn 0..7 x 16 cols)
// K staged 128 (8 stages), double-buf
// ---------------------------------------------------------------------------
#define OP_STG 21760
__global__ __launch_bounds__(512, 2) void oproj_kernel(
    const float* __restrict__ bo, const float* __restrict__ mask,
    float* __restrict__ out)
{
    extern __shared__ __half smh[];
    const int tid = threadIdx.x;
    const int wid = tid >> 5, lane = tid & 31;
    const int g = lane >> 2, c = lane & 3;
    const int wm = wid & 1, wn = wid >> 1;      // warp tile 16 x 16
    const int r0 = blockIdx.x * 32;
    const __half* abase = g_y1h + (size_t)r0 * HD;

    const int frow = tid >> 4, fc8 = (tid & 15) * 8;
#define OP_FILL(ks, buf) {                                                      \
        __half* As = smh + (buf) * OP_STG;                                      \
        __half* Bs = As + 4352;                                                 \
        const int k0 = (ks) * 128;                                              \
        cpa16(&As[frow * 136 + fc8], &abase[(size_t)frow * HD + k0 + fc8]);     \
        _Pragma("unroll")                                                       \
        for (int t = 0; t < 4; t++) {                                           \
            int row = frow + t * 32;                                            \
            cpa16(&Bs[row * 136 + fc8], &g_wot[(size_t)row * HD + k0 + fc8]);   \
        }                                                                       \
        CP_COMMIT(); }

    float acc[2][4];
#pragma unroll
    for (int nf = 0; nf < 2; nf++)
#pragma unroll
        for (int i = 0; i < 4; i++) acc[nf][i] = 0.0f;

    OP_FILL(0, 0);
    for (int ks = 0; ks < 8; ks++) {
        if (ks < 7) { OP_FILL(ks + 1, (ks + 1) & 1); CP_WAIT(1); }
        else        { CP_WAIT(0); }
        __syncthreads();
        const __half* As = smh + (ks & 1) * OP_STG;
        const __half* Bs = As + 4352;
#pragma unroll
        for (int kb = 0; kb < 8; kb++) {
            const int k16 = kb * 16 + 2 * c;
            unsigned a[4];
            int row = wm * 16;
            a[0] = *(const unsigned*)&As[(row + g) * 136 + k16];
            a[1] = *(const unsigned*)&As[(row + g + 8) * 136 + k16];
            a[2] = *(const unsigned*)&As[(row + g) * 136 + k16 + 8];
            a[3] = *(const unsigned*)&As[(row + g + 8) * 136 + k16 + 8];
#pragma unroll
            for (int nf = 0; nf < 2; nf++) {
                int col = wn * 16 + nf * 8;
                unsigned b[2];
                b[0] = *(const unsigned*)&Bs[(col + g) * 136 + k16];
                b[1] = *(const unsigned*)&Bs[(col + g) * 136 + k16 + 8];
                mma16(acc[nf], a, b);
            }
        }
        __syncthreads();
    }

#pragma unroll
    for (int rr = 0; rr < 2; rr++) {
        int row = r0 + wm * 16 + g + rr * 8;
        float mm = mask[row];
#pragma unroll
        for (int nf = 0; nf < 2; nf++) {
            int col = wn * 16 + nf * 8 + 2 * c;
            float v0 = (acc[nf][rr * 2 + 0] + bo[col]) * mm;
            float v1 = (acc[nf][rr * 2 + 1] + bo[col + 1]) * mm;
            *(float2*)&out[(size_t)row * DH + col] = make_float2(v0, v1);
        }
    }
}

// ---------------------------------------------------------------------------
extern "C" void kernel_launch(void* const* d_in, const int* in_sizes, int n_in,
                              void* d_out, int out_size)
{
    const float* x    = (const float*)d_in[0];
    const float* dist = (const float*)d_in[1];
    const float* mask = (const float*)d_in[2];
    const float* Wq   = (const float*)d_in[3];
    const float* bq   = (const float*)d_in[4];
    const float* Wk   = (const float*)d_in[5];
    const float* bk   = (const float*)d_in[6];
    const float* Wv   = (const float*)d_in[7];
    const float* bv   = (const float*)d_in[8];
    const float* Wo   = (const float*)d_in[9];
    const float* bo   = (const float*)d_in[10];
    float* out = (float*)d_out;

    const int proj_smem = (128 * PRSTR + 64 * PRSTR) * 2;              // 52224
    const int attn_smem = (17408 + 2*8704 + 2*8704 + 2*9216 + 9216) * 2 + 512 * 4; // 161792
    const int op_smem   = OP_STG * 2 * 2;                              // 87040

    static cudaStream_t s1;
    static cudaEvent_t ev_fork, ev_join;
    static int configured = 0;
    if (!configured) {
        cudaFuncSetAttribute(proj_kernel, cudaFuncAttributeMaxDynamicSharedMemorySize, proj_smem);
        cudaFuncSetAttribute(attn_kernel, cudaFuncAttributeMaxDynamicSharedMemorySize, attn_smem);
        cudaFuncSetAttribute(oproj_kernel, cudaFuncAttributeMaxDynamicSharedMemorySize, op_smem);
        cudaStreamCreateWithFlags(&s1, cudaStreamNonBlocking);
        cudaEventCreateWithFlags(&ev_fork, cudaEventDisableTiming);
        cudaEventCreateWithFlags(&ev_join, cudaEventDisableTiming);
        configured = 1;
    }

    // fork: dprep (only consumer is attn) runs concurrently with prep/wtrans/proj
    cudaEventRecord(ev_fork, 0);
    cudaStreamWaitEvent(s1, ev_fork, 0);
    dprep_kernel<<<4096, 256, 0, s1>>>(dist, mask);
    cudaEventRecord(ev_join, s1);

    prep_kernel<<<1024, 256>>>(x);
    wtrans_kernel<<<dim3(32, 32, 4), dim3(32, 8)>>>(Wq, Wk, Wv, Wo);
    proj_kernel<<<dim3(HD/64, NROWS/128, 3), 256, proj_smem>>>(mask, bq, bk, bv);

    // join: attn needs g_dh
    cudaStreamWaitEvent(0, ev_join, 0);
    attn_kernel<<<dim3(SEQ/128, BB*NH), 1024, attn_smem>>>();
    oproj_kernel<<<dim3(NROWS/32), 512, op_smem>>>(bo, mask, out);
}

// round 15
// speedup vs baseline: 1.2826x; 1.1906x over previous
#include <cuda_runtime.h>
#include <cuda_fp16.h>

#define BB   16
#define SEQ  512
#define NH   8
#define DH   128
#define HD   1024
#define NROWS (BB*SEQ)            // 8192
#define SCALE 0.08838834764831843f

// Scratch (no device allocation allowed)
__device__ __half g_q  [BB*NH*SEQ*DH]; // [B,H,N,D] masked*scaled fp16
__device__ __half g_k  [BB*NH*SEQ*DH]; // [B,H,N,D] masked fp16
__device__ __half g_v  [BB*NH*SEQ*DH]; // [B,H,N,D] masked fp16
__device__ __half g_dh [BB*SEQ*SEQ];   // dist + key-mask(-1e9), fp16
__device__ __half g_y1h[NROWS*HD];     // [B,N,H*D] attn out fp16
__device__ __half g_xh [NROWS*DH];     // x fp16
__device__ __half g_wqt[HD*DH];        // Wq^T [n][k] fp16
__device__ __half g_wkt[HD*DH];
__device__ __half g_wvt[HD*DH];
__device__ __half g_wot[DH*HD];        // Wo^T [n=128][k=1024] fp16

__device__ __forceinline__ void cpa16(void* dst_smem, const void* src_gmem) {
    unsigned s = (unsigned)__cvta_generic_to_shared(dst_smem);
    asm volatile("cp.async.cg.shared.global [%0], [%1], 16;\n" :: "r"(s), "l"(src_gmem));
}
#define CP_COMMIT() asm volatile("cp.async.commit_group;\n")
#define CP_WAIT(n)  asm volatile("cp.async.wait_group %0;\n" :: "n"(n))

// fp16 k16 mma, fp32 accum
__device__ __forceinline__ void mma16(float* d, const unsigned* a, const unsigned* b) {
    asm volatile(
        "mma.sync.aligned.m16n8k16.row.col.f32.f16.f16.f32 "
        "{%0,%1,%2,%3}, {%4,%5,%6,%7}, {%8,%9}, {%0,%1,%2,%3};"
        : "+f"(d[0]), "+f"(d[1]), "+f"(d[2]), "+f"(d[3])
        : "r"(a[0]), "r"(a[1]), "r"(a[2]), "r"(a[3]), "r"(b[0]), "r"(b[1]));
}
__device__ __forceinline__ unsigned smaddr(const void* p) {
    return (unsigned)__cvta_generic_to_shared(p);
}
__device__ __forceinline__ void ldsm4(unsigned* r, unsigned a) {
    asm volatile("ldmatrix.sync.aligned.m8n8.x4.shared.b16 {%0,%1,%2,%3}, [%4];"
        : "=r"(r[0]), "=r"(r[1]), "=r"(r[2]), "=r"(r[3]) : "r"(a));
}
__device__ __forceinline__ void ldsm4t(unsigned* r, unsigned a) {
    asm volatile("ldmatrix.sync.aligned.m8n8.x4.trans.shared.b16 {%0,%1,%2,%3}, [%4];"
        : "=r"(r[0]), "=r"(r[1]), "=r"(r[2]), "=r"(r[3]) : "r"(a));
}

// ---------------------------------------------------------------------------
// prep: x -> fp16. grid 1024 x 256
// ---------------------------------------------------------------------------
__global__ void prep_kernel(const float* __restrict__ x)
{
    int i = blockIdx.x * 256 + threadIdx.x;       // float4 index
    if (i < NROWS*DH/4) {
        float4 v = ((const float4*)x)[i];
        ((__half2*)g_xh)[i * 2 + 0] = __floats2half2_rn(v.x, v.y);
        ((__half2*)g_xh)[i * 2 + 1] = __floats2half2_rn(v.z, v.w);
    }
}

// ---------------------------------------------------------------------------
// weight transpose -> fp16: W[R=k][C=n] f32 -> Wt[C][R] h16. grid (32,32,4)
// ---------------------------------------------------------------------------
__global__ void wtrans_kernel(const float* __restrict__ Wq, const float* __restrict__ Wk,
                              const float* __restrict__ Wv, const float* __restrict__ Wo)
{
    __shared__ float t[32][33];
    const int z = blockIdx.z;
    const float* src = (z == 0) ? Wq : (z == 1) ? Wk : (z == 2) ? Wv : Wo;
    __half* dst = (z == 0) ? g_wqt : (z == 1) ? g_wkt : (z == 2) ? g_wvt : g_wot;
    const int R = (z < 3) ? DH : HD;
    const int C = (z < 3) ? HD : DH;
    if ((int)blockIdx.x * 32 >= C || (int)blockIdx.y * 32 >= R) return;
    const int tx = threadIdx.x, ty = threadIdx.y;
    const int r = blockIdx.y * 32, c = blockIdx.x * 32;
#pragma unroll
    for (int j = 0; j < 4; j++)
        t[ty + j*8][tx] = src[(size_t)(r + ty + j*8) * C + c + tx];
    __syncthreads();
#pragma unroll
    for (int j = 0; j < 4; j++)
        dst[(size_t)(c + ty + j*8) * R + r + tx] = __float2half_rn(t[tx][ty + j*8]);
}

// ---------------------------------------------------------------------------
// dprep: g_dh = fp16(dist + (mask[key]? 0 : -1e9)). grid 4096 x 256
// ---------------------------------------------------------------------------
__global__ void dprep_kernel(const float* __restrict__ dist,
                             const float* __restrict__ mask)
{
    size_t i4 = (size_t)blockIdx.x * 256 + threadIdx.x;
    float4 v = ((const float4*)dist)[i4];
    int m = (int)(i4 & 127) * 4;
    int b = (int)(i4 >> 16);
    const float* mrow = mask + b * SEQ;
    float a0 = v.x + ((mrow[m + 0] == 0.0f) ? -1e9f : 0.0f);
    float a1 = v.y + ((mrow[m + 1] == 0.0f) ? -1e9f : 0.0f);
    float a2 = v.z + ((mrow[m + 2] == 0.0f) ? -1e9f : 0.0f);
    float a3 = v.w + ((mrow[m + 3] == 0.0f) ? -1e9f : 0.0f);
    ((__half2*)g_dh)[i4 * 2 + 0] = __floats2half2_rn(a0, a1);
    ((__half2*)g_dh)[i4 * 2 + 1] = __floats2half2_rn(a2, a3);
}

// ---------------------------------------------------------------------------
// QKV projection fp16, SINGLE-STAGE K=128 (unchanged)
// ---------------------------------------------------------------------------
#define PRSTR 136
__global__ __launch_bounds__(256, 4) void proj_kernel(
    const float* __restrict__ mask,
    const float* __restrict__ bq, const float* __restrict__ bk,
    const float* __restrict__ bv)
{
    extern __shared__ __half smh[];
    __half* As = smh;                 // [128][136]
    __half* Bs = As + 128 * PRSTR;    // [64][136]
    const int tid = threadIdx.x;
    const int wid = tid >> 5, lane = tid & 31;
    const int g = lane >> 2, c = lane & 3;
    const int wm = wid & 3, wn = wid >> 2;       // warp tile 32 x 32
    const int c0 = blockIdx.x * 64;
    const int r0 = blockIdx.y * 128;
    const int sel = blockIdx.z;
    const __half* Wt  = (sel == 0) ? g_wqt : (sel == 1) ? g_wkt : g_wvt;
    const float* bias = (sel == 0) ? bq : (sel == 1) ? bk : bv;
    __half*      out  = (sel == 0) ? g_q : (sel == 1) ? g_k : g_v;
    const float extra = (sel == 0) ? SCALE : 1.0f;
    const __half* xbase = g_xh + (size_t)r0 * DH;
    const __half* wbase = Wt + (size_t)c0 * DH;

    const int frow = tid >> 4, fc8 = (tid & 15) * 8;
#pragma unroll
    for (int t = 0; t < 8; t++) {
        int row = frow + t * 16;
        cpa16(&As[row * PRSTR + fc8], &xbase[(size_t)row * DH + fc8]);
    }
#pragma unroll
    for (int t = 0; t < 4; t++) {
        int row = frow + t * 16;
        cpa16(&Bs[row * PRSTR + fc8], &wbase[(size_t)row * DH + fc8]);
    }
    CP_COMMIT();

    float acc[2][4][4];
#pragma unroll
    for (int mf = 0; mf < 2; mf++)
#pragma unroll
        for (int nf = 0; nf < 4; nf++)
#pragma unroll
            for (int i = 0; i < 4; i++) acc[mf][nf][i] = 0.0f;

    CP_WAIT(0);
    __syncthreads();

#pragma unroll
    for (int kb = 0; kb < 8; kb++) {
        const int k16 = kb * 16 + 2 * c;
        unsigned a[2][4];
#pragma unroll
        for (int mf = 0; mf < 2; mf++) {
            int row = wm * 32 + mf * 16;
            a[mf][0] = *(const unsigned*)&As[(row + g) * PRSTR + k16];
            a[mf][1] = *(const unsigned*)&As[(row + g + 8) * PRSTR + k16];
            a[mf][2] = *(const unsigned*)&As[(row + g) * PRSTR + k16 + 8];
            a[mf][3] = *(const unsigned*)&As[(row + g + 8) * PRSTR + k16 + 8];
        }
#pragma unroll
        for (int nf = 0; nf < 4; nf++) {
            int col = wn * 32 + nf * 8;
            unsigned b[2];
            b[0] = *(const unsigned*)&Bs[(col + g) * PRSTR + k16];
            b[1] = *(const unsigned*)&Bs[(col + g) * PRSTR + k16 + 8];
            mma16(acc[0][nf], a[0], b);
            mma16(acc[1][nf], a[1], b);
        }
    }

#pragma unroll
    for (int mf = 0; mf < 2; mf++) {
#pragma unroll
        for (int rr = 0; rr < 2; rr++) {
            int row = r0 + wm * 32 + mf * 16 + g + rr * 8;
            int bI = row >> 9, n = row & 511;
            float mm = mask[row] * extra;
#pragma unroll
            for (int nf = 0; nf < 4; nf++) {
                int col = c0 + wn * 32 + nf * 8 + 2 * c;
                int h = col >> 7, d = col & 127;
                float v0 = (acc[mf][nf][rr * 2 + 0] + bias[col]) * mm;
                float v1 = (acc[mf][nf][rr * 2 + 1] + bias[col + 1]) * mm;
                *(__half2*)&out[(((size_t)bI * NH + h) * SEQ + n) * DH + d] =
                    __floats2half2_rn(v0, v1);
            }
        }
    }
}

// ---------------------------------------------------------------------------
// Flash attention fp16, FA2-style: 8 warps x 256 thr, each warp owns 16 rows
// x ALL 64 keys x ALL 128 D. P stays in registers. Fragment permutation FIXED:
// A-frag order = {(g,klo),(g+8,klo),(g,khi),(g+8,khi)}.
// smem: Qs[128][136] + Ks[64][136] + V2[2][64][136] + Ds[128][72] = 105472 B
// ---------------------------------------------------------------------------
#define QSTR 136
#define DSTR 72
__global__ __launch_bounds__(256, 2) void attn_kernel()
{
    extern __shared__ __half smh[];
    __half* Qs = smh;                    // [128][136]
    __half* Ks = Qs + 128 * QSTR;        // [64][136] single
    __half* V2 = Ks + 64 * QSTR;         // 2 x [64][136]
    __half* Ds = V2 + 2 * 64 * QSTR;     // [128][72] single

    const int tid = threadIdx.x;
    const int wid = tid >> 5, lane = tid & 31;
    const int g = lane >> 2, c = lane & 3;
    const int bh = blockIdx.y;
    const int b = bh >> 3, h = bh & 7;
    const int q0 = blockIdx.x * 128;
    const int m0 = wid * 16;             // warp owns rows m0..m0+15

    const __half* qbase = g_q + (size_t)bh * SEQ * DH;
    const __half* kbase = g_k + (size_t)bh * SEQ * DH;
    const __half* vbase = g_v + (size_t)bh * SEQ * DH;
    const __half* dbase = g_dh + ((size_t)b * SEQ + q0) * SEQ;

    const int frow = tid >> 4, fc8 = (tid & 15) * 8;   // K/V: 64 rows x 16 chunks
    const int drow = tid >> 3, dc8 = (tid & 7) * 8;    // D: 128 rows x 8 chunks

#define FILL_KD(kt) {                                                           \
        _Pragma("unroll")                                                       \
        for (int t = 0; t < 4; t++) {                                           \
            int key = frow + t * 16;                                            \
            cpa16(&Ks[key * QSTR + fc8],                                        \
                  &kbase[(size_t)((kt) * 64 + key) * DH + fc8]);                \
        }                                                                       \
        _Pragma("unroll")                                                       \
        for (int t = 0; t < 4; t++) {                                           \
            int row = drow + t * 32;                                            \
            cpa16(&Ds[row * DSTR + dc8],                                        \
                  &dbase[(size_t)row * SEQ + (kt) * 64 + dc8]);                 \
        }                                                                       \
        CP_COMMIT(); }
#define FILL_V(kt) {                                                            \
        __half* Vs = V2 + ((kt) & 1) * 64 * QSTR;                               \
        _Pragma("unroll")                                                       \
        for (int t = 0; t < 4; t++) {                                           \
            int key = frow + t * 16;                                            \
            cpa16(&Vs[key * QSTR + fc8],                                        \
                  &vbase[(size_t)((kt) * 64 + key) * DH + fc8]);                \
        }                                                                       \
        CP_COMMIT(); }

    // prologue: Q + K(0) + D(0), then V(0)
    {
#pragma unroll
        for (int t = 0; t < 8; t++) {
            int row = frow + t * 16;
            cpa16(&Qs[row * QSTR + fc8], &qbase[(size_t)(q0 + row) * DH + fc8]);
        }
        FILL_KD(0);
        FILL_V(0);
    }

    float O[16][4];
#pragma unroll
    for (int nf = 0; nf < 16; nf++)
#pragma unroll
        for (int i = 0; i < 4; i++) O[nf][i] = 0.0f;
    float l_t[2] = {0.0f, 0.0f};

    // ldmatrix lane coords
    const int arow = m0 + (lane & 7) + (((lane >> 3) & 1) << 3);
    const int akoff = (lane >> 4) << 3;
    const unsigned aQ = smaddr(&Qs[arow * QSTR + akoff]);
    unsigned bK[4];
#pragma unroll
    for (int t = 0; t < 4; t++)
        bK[t] = smaddr(&Ks[(t * 16 + (lane & 7) + ((lane >> 4) << 3)) * QSTR +
                           (((lane >> 3) & 1) << 3)]);

    for (int kt = 0; kt < 8; kt++) {
        const __half* Vs = V2 + (kt & 1) * 64 * QSTR;
        CP_WAIT(0);                       // K/D(kt) + V(kt) landed
        __syncthreads();                  // all warps past PV(kt-1)
        if (kt < 7) FILL_V(kt + 1);       // other V buffer; safe

        // S init from dist tile (dist+mask pre-fused fp16)
        float s[8][4];
#pragma unroll
        for (int nf = 0; nf < 8; nf++) {
            int gcol = nf * 8 + 2 * c;
            float2 d0 = __half22float2(*(const __half2*)&Ds[(m0 + g) * DSTR + gcol]);
            float2 d1 = __half22float2(*(const __half2*)&Ds[(m0 + g + 8) * DSTR + gcol]);
            s[nf][0] = d0.x; s[nf][1] = d0.y;
            s[nf][2] = d1.x; s[nf][3] = d1.y;
        }
        // S += Q @ K^T : 16 rows x 64 keys, k = 128
#pragma unroll
        for (int kb = 0; kb < 8; kb++) {
            unsigned a[4];
            ldsm4(a, aQ + kb * 32);
#pragma unroll
            for (int t = 0; t < 4; t++) {
                unsigned bk_[4];
                ldsm4(bk_, bK[t] + kb * 32);
                mma16(s[2 * t], a, bk_);
                mma16(s[2 * t + 1], a, bk_ + 2);
            }
        }
        __syncthreads();                  // all warps done reading Ks/Ds
        if (kt < 7) FILL_KD(kt + 1);      // single buffers; now safe

        // softmax in registers -> pack to PV A-fragments
        // A-frag order: {(row g, k-lo), (row g+8, k-lo), (row g, k-hi), (row g+8, k-hi)}
        unsigned pP[4][4];                // [key-block t][frag reg]
#pragma unroll
        for (int t = 0; t < 4; t++) {
            float e00 = __expf(s[2*t][0]),   e01 = __expf(s[2*t][1]);   // g,   k-lo
            float e02 = __expf(s[2*t][2]),   e03 = __expf(s[2*t][3]);   // g+8, k-lo
            float e10 = __expf(s[2*t+1][0]), e11 = __expf(s[2*t+1][1]); // g,   k-hi
            float e12 = __expf(s[2*t+1][2]), e13 = __expf(s[2*t+1][3]); // g+8, k-hi
            l_t[0] += e00 + e01 + e10 + e11;     // row g
            l_t[1] += e02 + e03 + e12 + e13;     // row g+8
            __half2 h0 = __floats2half2_rn(e00, e01);   // (g,   k-lo)
            __half2 h1 = __floats2half2_rn(e02, e03);   // (g+8, k-lo)
            __half2 h2 = __floats2half2_rn(e10, e11);   // (g,   k-hi)
            __half2 h3 = __floats2half2_rn(e12, e13);   // (g+8, k-hi)
            pP[t][0] = *(unsigned*)&h0;
            pP[t][1] = *(unsigned*)&h1;
            pP[t][2] = *(unsigned*)&h2;
            pP[t][3] = *(unsigned*)&h3;
        }

        // O += P @ V : 16 rows x 128 D, k = 64 (P from registers)
#pragma unroll
        for (int t = 0; t < 4; t++) {
#pragma unroll
            for (int nb = 0; nb < 8; nb++) {
                unsigned v[4];
                unsigned vaddr = smaddr(&Vs[(t * 16 + (lane & 15)) * QSTR +
                                            nb * 16 + ((lane >> 4) << 3)]);
                ldsm4t(v, vaddr);
                mma16(O[2 * nb], pP[t], v);
                mma16(O[2 * nb + 1], pP[t], v + 2);
            }
        }
    }

    // l: quad-lane reduce only (warp owns all 64 keys of each tile)
    float inv[2];
#pragma unroll
    for (int rr = 0; rr < 2; rr++) {
        float lv = l_t[rr];
        lv += __shfl_xor_sync(0xffffffffu, lv, 1);
        lv += __shfl_xor_sync(0xffffffffu, lv, 2);
        inv[rr] = (lv > 0.0f) ? 1.0f / lv : 0.0f;
    }

#pragma unroll
    for (int rr = 0; rr < 2; rr++) {
        int row = m0 + g + rr * 8;
        __half* orow = g_y1h + ((size_t)b * SEQ + q0 + row) * HD + h * DH;
#pragma unroll
        for (int nf = 0; nf < 16; nf++) {
            int col = nf * 8 + 2 * c;
            *(__half2*)&orow[col] = __floats2half2_rn(O[nf][rr * 2 + 0] * inv[rr],
                                                      O[nf][rr * 2 + 1] * inv[rr]);
        }
    }
}

// ---------------------------------------------------------------------------
// Output projection fp16 (unchanged)
// ---------------------------------------------------------------------------
#define OP_STG 21760
__global__ __launch_bounds__(512, 2) void oproj_kernel(
    const float* __restrict__ bo, const float* __restrict__ mask,
    float* __restrict__ out)
{
    extern __shared__ __half smh[];
    const int tid = threadIdx.x;
    const int wid = tid >> 5, lane = tid & 31;
    const int g = lane >> 2, c = lane & 3;
    const int wm = wid & 1, wn = wid >> 1;      // warp tile 16 x 16
    const int r0 = blockIdx.x * 32;
    const __half* abase = g_y1h + (size_t)r0 * HD;

    const int frow = tid >> 4, fc8 = (tid & 15) * 8;
#define OP_FILL(ks, buf) {                                                      \
        __half* As = smh + (buf) * OP_STG;                                      \
        __half* Bs = As + 4352;                                                 \
        const int k0 = (ks) * 128;                                              \
        cpa16(&As[frow * 136 + fc8], &abase[(size_t)frow * HD + k0 + fc8]);     \
        _Pragma("unroll")                                                       \
        for (int t = 0; t < 4; t++) {                                           \
            int row = frow + t * 32;                                            \
            cpa16(&Bs[row * 136 + fc8], &g_wot[(size_t)row * HD + k0 + fc8]);   \
        }                                                                       \
        CP_COMMIT(); }

    float acc[2][4];
#pragma unroll
    for (int nf = 0; nf < 2; nf++)
#pragma unroll
        for (int i = 0; i < 4; i++) acc[nf][i] = 0.0f;

    OP_FILL(0, 0);
    for (int ks = 0; ks < 8; ks++) {
        if (ks < 7) { OP_FILL(ks + 1, (ks + 1) & 1); CP_WAIT(1); }
        else        { CP_WAIT(0); }
        __syncthreads();
        const __half* As = smh + (ks & 1) * OP_STG;
        const __half* Bs = As + 4352;
#pragma unroll
        for (int kb = 0; kb < 8; kb++) {
            const int k16 = kb * 16 + 2 * c;
            unsigned a[4];
            int row = wm * 16;
            a[0] = *(const unsigned*)&As[(row + g) * 136 + k16];
            a[1] = *(const unsigned*)&As[(row + g + 8) * 136 + k16];
            a[2] = *(const unsigned*)&As[(row + g) * 136 + k16 + 8];
            a[3] = *(const unsigned*)&As[(row + g + 8) * 136 + k16 + 8];
#pragma unroll
            for (int nf = 0; nf < 2; nf++) {
                int col = wn * 16 + nf * 8;
                unsigned b[2];
                b[0] = *(const unsigned*)&Bs[(col + g) * 136 + k16];
                b[1] = *(const unsigned*)&Bs[(col + g) * 136 + k16 + 8];
                mma16(acc[nf], a, b);
            }
        }
        __syncthreads();
    }

#pragma unroll
    for (int rr = 0; rr < 2; rr++) {
        int row = r0 + wm * 16 + g + rr * 8;
        float mm = mask[row];
#pragma unroll
        for (int nf = 0; nf < 2; nf++) {
            int col = wn * 16 + nf * 8 + 2 * c;
            float v0 = (acc[nf][rr * 2 + 0] + bo[col]) * mm;
            float v1 = (acc[nf][rr * 2 + 1] + bo[col + 1]) * mm;
            *(float2*)&out[(size_t)row * DH + col] = make_float2(v0, v1);
        }
    }
}

// ---------------------------------------------------------------------------
extern "C" void kernel_launch(void* const* d_in, const int* in_sizes, int n_in,
                              void* d_out, int out_size)
{
    const float* x    = (const float*)d_in[0];
    const float* dist = (const float*)d_in[1];
    const float* mask = (const float*)d_in[2];
    const float* Wq   = (const float*)d_in[3];
    const float* bq   = (const float*)d_in[4];
    const float* Wk   = (const float*)d_in[5];
    const float* bk   = (const float*)d_in[6];
    const float* Wv   = (const float*)d_in[7];
    const float* bv   = (const float*)d_in[8];
    const float* Wo   = (const float*)d_in[9];
    const float* bo   = (const float*)d_in[10];
    float* out = (float*)d_out;

    const int proj_smem = (128 * PRSTR + 64 * PRSTR) * 2;              // 52224
    const int attn_smem = (128*QSTR + 64*QSTR + 2*64*QSTR + 128*DSTR) * 2; // 105472
    const int op_smem   = OP_STG * 2 * 2;                              // 87040

    static cudaStream_t s1;
    static cudaEvent_t ev_fork, ev_join;
    static int configured = 0;
    if (!configured) {
        cudaFuncSetAttribute(proj_kernel, cudaFuncAttributeMaxDynamicSharedMemorySize, proj_smem);
        cudaFuncSetAttribute(attn_kernel, cudaFuncAttributeMaxDynamicSharedMemorySize, attn_smem);
        cudaFuncSetAttribute(oproj_kernel, cudaFuncAttributeMaxDynamicSharedMemorySize, op_smem);
        cudaStreamCreateWithFlags(&s1, cudaStreamNonBlocking);
        cudaEventCreateWithFlags(&ev_fork, cudaEventDisableTiming);
        cudaEventCreateWithFlags(&ev_join, cudaEventDisableTiming);
        configured = 1;
    }

    // fork: dprep (only consumer is attn) runs concurrently with prep/wtrans/proj
    cudaEventRecord(ev_fork, 0);
    cudaStreamWaitEvent(s1, ev_fork, 0);
    dprep_kernel<<<4096, 256, 0, s1>>>(dist, mask);
    cudaEventRecord(ev_join, s1);

    prep_kernel<<<1024, 256>>>(x);
    wtrans_kernel<<<dim3(32, 32, 4), dim3(32, 8)>>>(Wq, Wk, Wv, Wo);
    proj_kernel<<<dim3(HD/64, NROWS/128, 3), 256, proj_smem>>>(mask, bq, bk, bv);

    // join: attn needs g_dh
    cudaStreamWaitEvent(0, ev_join, 0);
    attn_kernel<<<dim3(SEQ/128, BB*NH), 256, attn_smem>>>();
    oproj_kernel<<<dim3(NROWS/32), 512, op_smem>>>(bo, mask, out);
}

// round 16
// speedup vs baseline: 1.3167x; 1.0265x over previous
#include <cuda_runtime.h>
#include <cuda_fp16.h>

#define BB   16
#define SEQ  512
#define NH   8
#define DH   128
#define HD   1024
#define NROWS (BB*SEQ)            // 8192
#define SCALE 0.08838834764831843f

// Scratch (no device allocation allowed)
__device__ __half g_q  [BB*NH*SEQ*DH]; // [B,H,N,D] masked*scaled fp16
__device__ __half g_k  [BB*NH*SEQ*DH]; // [B,H,N,D] masked fp16
__device__ __half g_v  [BB*NH*SEQ*DH]; // [B,H,N,D] masked fp16
__device__ __half g_dh [BB*SEQ*SEQ];   // dist + key-mask(-1e9), fp16
__device__ __half g_y1h[NROWS*HD];     // [B,N,H*D] attn out fp16
__device__ __half g_xh [NROWS*DH];     // x fp16
__device__ __half g_wqt[HD*DH];        // Wq^T [n][k] fp16
__device__ __half g_wkt[HD*DH];
__device__ __half g_wvt[HD*DH];
__device__ __half g_wot[DH*HD];        // Wo^T [n=128][k=1024] fp16

__device__ __forceinline__ void cpa16(void* dst_smem, const void* src_gmem) {
    unsigned s = (unsigned)__cvta_generic_to_shared(dst_smem);
    asm volatile("cp.async.cg.shared.global [%0], [%1], 16;\n" :: "r"(s), "l"(src_gmem));
}
#define CP_COMMIT() asm volatile("cp.async.commit_group;\n")
#define CP_WAIT(n)  asm volatile("cp.async.wait_group %0;\n" :: "n"(n))

// fp16 k16 mma, fp32 accum
__device__ __forceinline__ void mma16(float* d, const unsigned* a, const unsigned* b) {
    asm volatile(
        "mma.sync.aligned.m16n8k16.row.col.f32.f16.f16.f32 "
        "{%0,%1,%2,%3}, {%4,%5,%6,%7}, {%8,%9}, {%0,%1,%2,%3};"
        : "+f"(d[0]), "+f"(d[1]), "+f"(d[2]), "+f"(d[3])
        : "r"(a[0]), "r"(a[1]), "r"(a[2]), "r"(a[3]), "r"(b[0]), "r"(b[1]));
}
__device__ __forceinline__ unsigned smaddr(const void* p) {
    return (unsigned)__cvta_generic_to_shared(p);
}
__device__ __forceinline__ void ldsm4(unsigned* r, unsigned a) {
    asm volatile("ldmatrix.sync.aligned.m8n8.x4.shared.b16 {%0,%1,%2,%3}, [%4];"
        : "=r"(r[0]), "=r"(r[1]), "=r"(r[2]), "=r"(r[3]) : "r"(a));
}
__device__ __forceinline__ void ldsm4t(unsigned* r, unsigned a) {
    asm volatile("ldmatrix.sync.aligned.m8n8.x4.trans.shared.b16 {%0,%1,%2,%3}, [%4];"
        : "=r"(r[0]), "=r"(r[1]), "=r"(r[2]), "=r"(r[3]) : "r"(a));
}

// ---------------------------------------------------------------------------
// prep: x -> fp16. grid 1024 x 256
// ---------------------------------------------------------------------------
__global__ void prep_kernel(const float* __restrict__ x)
{
    int i = blockIdx.x * 256 + threadIdx.x;       // float4 index
    if (i < NROWS*DH/4) {
        float4 v = ((const float4*)x)[i];
        ((__half2*)g_xh)[i * 2 + 0] = __floats2half2_rn(v.x, v.y);
        ((__half2*)g_xh)[i * 2 + 1] = __floats2half2_rn(v.z, v.w);
    }
}

// ---------------------------------------------------------------------------
// weight transpose -> fp16: W[R=k][C=n] f32 -> Wt[C][R] h16. grid (32,32,4)
// ---------------------------------------------------------------------------
__global__ void wtrans_kernel(const float* __restrict__ Wq, const float* __restrict__ Wk,
                              const float* __restrict__ Wv, const float* __restrict__ Wo)
{
    __shared__ float t[32][33];
    const int z = blockIdx.z;
    const float* src = (z == 0) ? Wq : (z == 1) ? Wk : (z == 2) ? Wv : Wo;
    __half* dst = (z == 0) ? g_wqt : (z == 1) ? g_wkt : (z == 2) ? g_wvt : g_wot;
    const int R = (z < 3) ? DH : HD;
    const int C = (z < 3) ? HD : DH;
    if ((int)blockIdx.x * 32 >= C || (int)blockIdx.y * 32 >= R) return;
    const int tx = threadIdx.x, ty = threadIdx.y;
    const int r = blockIdx.y * 32, c = blockIdx.x * 32;
#pragma unroll
    for (int j = 0; j < 4; j++)
        t[ty + j*8][tx] = src[(size_t)(r + ty + j*8) * C + c + tx];
    __syncthreads();
#pragma unroll
    for (int j = 0; j < 4; j++)
        dst[(size_t)(c + ty + j*8) * R + r + tx] = __float2half_rn(t[tx][ty + j*8]);
}

// ---------------------------------------------------------------------------
// dprep: g_dh = fp16(dist + (mask[key]? 0 : -1e9)). grid 4096 x 256
// ---------------------------------------------------------------------------
__global__ void dprep_kernel(const float* __restrict__ dist,
                             const float* __restrict__ mask)
{
    size_t i4 = (size_t)blockIdx.x * 256 + threadIdx.x;
    float4 v = ((const float4*)dist)[i4];
    int m = (int)(i4 & 127) * 4;
    int b = (int)(i4 >> 16);
    const float* mrow = mask + b * SEQ;
    float a0 = v.x + ((mrow[m + 0] == 0.0f) ? -1e9f : 0.0f);
    float a1 = v.y + ((mrow[m + 1] == 0.0f) ? -1e9f : 0.0f);
    float a2 = v.z + ((mrow[m + 2] == 0.0f) ? -1e9f : 0.0f);
    float a3 = v.w + ((mrow[m + 3] == 0.0f) ? -1e9f : 0.0f);
    ((__half2*)g_dh)[i4 * 2 + 0] = __floats2half2_rn(a0, a1);
    ((__half2*)g_dh)[i4 * 2 + 1] = __floats2half2_rn(a2, a3);
}

// ---------------------------------------------------------------------------
// QKV projection fp16, SINGLE-STAGE K=128, ldmatrix fragment loads
// grid (HD/64, NROWS/128, 3), 256 thr; smem As[128][136]+Bs[64][136], 4/SM
// ---------------------------------------------------------------------------
#define PRSTR 136
__global__ __launch_bounds__(256, 4) void proj_kernel(
    const float* __restrict__ mask,
    const float* __restrict__ bq, const float* __restrict__ bk,
    const float* __restrict__ bv)
{
    extern __shared__ __half smh[];
    __half* As = smh;                 // [128][136]
    __half* Bs = As + 128 * PRSTR;    // [64][136]
    const int tid = threadIdx.x;
    const int wid = tid >> 5, lane = tid & 31;
    const int g = lane >> 2, c = lane & 3;
    const int wm = wid & 3, wn = wid >> 2;       // warp tile 32 x 32
    const int c0 = blockIdx.x * 64;
    const int r0 = blockIdx.y * 128;
    const int sel = blockIdx.z;
    const __half* Wt  = (sel == 0) ? g_wqt : (sel == 1) ? g_wkt : g_wvt;
    const float* bias = (sel == 0) ? bq : (sel == 1) ? bk : bv;
    __half*      out  = (sel == 0) ? g_q : (sel == 1) ? g_k : g_v;
    const float extra = (sel == 0) ? SCALE : 1.0f;
    const __half* xbase = g_xh + (size_t)r0 * DH;
    const __half* wbase = Wt + (size_t)c0 * DH;

    const int frow = tid >> 4, fc8 = (tid & 15) * 8;
#pragma unroll
    for (int t = 0; t < 8; t++) {
        int row = frow + t * 16;
        cpa16(&As[row * PRSTR + fc8], &xbase[(size_t)row * DH + fc8]);
    }
#pragma unroll
    for (int t = 0; t < 4; t++) {
        int row = frow + t * 16;
        cpa16(&Bs[row * PRSTR + fc8], &wbase[(size_t)row * DH + fc8]);
    }
    CP_COMMIT();

    float acc[2][4][4];
#pragma unroll
    for (int mf = 0; mf < 2; mf++)
#pragma unroll
        for (int nf = 0; nf < 4; nf++)
#pragma unroll
            for (int i = 0; i < 4; i++) acc[mf][nf][i] = 0.0f;

    CP_WAIT(0);
    __syncthreads();

    // ldmatrix base addresses (same lane mapping as attn's proven aQ/bK)
    unsigned aA[2], bB[2];
#pragma unroll
    for (int mf = 0; mf < 2; mf++)
        aA[mf] = smaddr(&As[(wm * 32 + mf * 16 + (lane & 7) +
                             (((lane >> 3) & 1) << 3)) * PRSTR +
                            ((lane >> 4) << 3)]);
#pragma unroll
    for (int p = 0; p < 2; p++)
        bB[p] = smaddr(&Bs[(wn * 32 + p * 16 + (lane & 7) +
                            ((lane >> 4) << 3)) * PRSTR +
                           (((lane >> 3) & 1) << 3)]);

#pragma unroll
    for (int kb = 0; kb < 8; kb++) {
        unsigned a0[4], a1[4];
        ldsm4(a0, aA[0] + kb * 32);
        ldsm4(a1, aA[1] + kb * 32);
#pragma unroll
        for (int p = 0; p < 2; p++) {
            unsigned bb[4];
            ldsm4(bb, bB[p] + kb * 32);
            mma16(acc[0][2 * p],     a0, bb);
            mma16(acc[0][2 * p + 1], a0, bb + 2);
            mma16(acc[1][2 * p],     a1, bb);
            mma16(acc[1][2 * p + 1], a1, bb + 2);
        }
    }

#pragma unroll
    for (int mf = 0; mf < 2; mf++) {
#pragma unroll
        for (int rr = 0; rr < 2; rr++) {
            int row = r0 + wm * 32 + mf * 16 + g + rr * 8;
            int bI = row >> 9, n = row & 511;
            float mm = mask[row] * extra;
#pragma unroll
            for (int nf = 0; nf < 4; nf++) {
                int col = c0 + wn * 32 + nf * 8 + 2 * c;
                int h = col >> 7, d = col & 127;
                float v0 = (acc[mf][nf][rr * 2 + 0] + bias[col]) * mm;
                float v1 = (acc[mf][nf][rr * 2 + 1] + bias[col + 1]) * mm;
                *(__half2*)&out[(((size_t)bI * NH + h) * SEQ + n) * DH + d] =
                    __floats2half2_rn(v0, v1);
            }
        }
    }
}

// ---------------------------------------------------------------------------
// Flash attention fp16, FA2-style (unchanged from R15)
// ---------------------------------------------------------------------------
#define QSTR 136
#define DSTR 72
__global__ __launch_bounds__(256, 2) void attn_kernel()
{
    extern __shared__ __half smh[];
    __half* Qs = smh;                    // [128][136]
    __half* Ks = Qs + 128 * QSTR;        // [64][136] single
    __half* V2 = Ks + 64 * QSTR;         // 2 x [64][136]
    __half* Ds = V2 + 2 * 64 * QSTR;     // [128][72] single

    const int tid = threadIdx.x;
    const int wid = tid >> 5, lane = tid & 31;
    const int g = lane >> 2, c = lane & 3;
    const int bh = blockIdx.y;
    const int b = bh >> 3, h = bh & 7;
    const int q0 = blockIdx.x * 128;
    const int m0 = wid * 16;             // warp owns rows m0..m0+15

    const __half* qbase = g_q + (size_t)bh * SEQ * DH;
    const __half* kbase = g_k + (size_t)bh * SEQ * DH;
    const __half* vbase = g_v + (size_t)bh * SEQ * DH;
    const __half* dbase = g_dh + ((size_t)b * SEQ + q0) * SEQ;

    const int frow = tid >> 4, fc8 = (tid & 15) * 8;   // K/V: 64 rows x 16 chunks
    const int drow = tid >> 3, dc8 = (tid & 7) * 8;    // D: 128 rows x 8 chunks

#define FILL_KD(kt) {                                                           \
        _Pragma("unroll")                                                       \
        for (int t = 0; t < 4; t++) {                                           \
            int key = frow + t * 16;                                            \
            cpa16(&Ks[key * QSTR + fc8],                                        \
                  &kbase[(size_t)((kt) * 64 + key) * DH + fc8]);                \
        }                                                                       \
        _Pragma("unroll")                                                       \
        for (int t = 0; t < 4; t++) {                                           \
            int row = drow + t * 32;                                            \
            cpa16(&Ds[row * DSTR + dc8],                                        \
                  &dbase[(size_t)row * SEQ + (kt) * 64 + dc8]);                 \
        }                                                                       \
        CP_COMMIT(); }
#define FILL_V(kt) {                                                            \
        __half* Vs = V2 + ((kt) & 1) * 64 * QSTR;                               \
        _Pragma("unroll")                                                       \
        for (int t = 0; t < 4; t++) {                                           \
            int key = frow + t * 16;                                            \
            cpa16(&Vs[key * QSTR + fc8],                                        \
                  &vbase[(size_t)((kt) * 64 + key) * DH + fc8]);                \
        }                                                                       \
        CP_COMMIT(); }

    // prologue: Q + K(0) + D(0), then V(0)
    {
#pragma unroll
        for (int t = 0; t < 8; t++) {
            int row = frow + t * 16;
            cpa16(&Qs[row * QSTR + fc8], &qbase[(size_t)(q0 + row) * DH + fc8]);
        }
        FILL_KD(0);
        FILL_V(0);
    }

    float O[16][4];
#pragma unroll
    for (int nf = 0; nf < 16; nf++)
#pragma unroll
        for (int i = 0; i < 4; i++) O[nf][i] = 0.0f;
    float l_t[2] = {0.0f, 0.0f};

    // ldmatrix lane coords
    const int arow = m0 + (lane & 7) + (((lane >> 3) & 1) << 3);
    const int akoff = (lane >> 4) << 3;
    const unsigned aQ = smaddr(&Qs[arow * QSTR + akoff]);
    unsigned bK[4];
#pragma unroll
    for (int t = 0; t < 4; t++)
        bK[t] = smaddr(&Ks[(t * 16 + (lane & 7) + ((lane >> 4) << 3)) * QSTR +
                           (((lane >> 3) & 1) << 3)]);

    for (int kt = 0; kt < 8; kt++) {
        const __half* Vs = V2 + (kt & 1) * 64 * QSTR;
        CP_WAIT(0);                       // K/D(kt) + V(kt) landed
        __syncthreads();                  // all warps past PV(kt-1)
        if (kt < 7) FILL_V(kt + 1);       // other V buffer; safe

        // S init from dist tile (dist+mask pre-fused fp16)
        float s[8][4];
#pragma unroll
        for (int nf = 0; nf < 8; nf++) {
            int gcol = nf * 8 + 2 * c;
            float2 d0 = __half22float2(*(const __half2*)&Ds[(m0 + g) * DSTR + gcol]);
            float2 d1 = __half22float2(*(const __half2*)&Ds[(m0 + g + 8) * DSTR + gcol]);
            s[nf][0] = d0.x; s[nf][1] = d0.y;
            s[nf][2] = d1.x; s[nf][3] = d1.y;
        }
        // S += Q @ K^T : 16 rows x 64 keys, k = 128
#pragma unroll
        for (int kb = 0; kb < 8; kb++) {
            unsigned a[4];
            ldsm4(a, aQ + kb * 32);
#pragma unroll
            for (int t = 0; t < 4; t++) {
                unsigned bk_[4];
                ldsm4(bk_, bK[t] + kb * 32);
                mma16(s[2 * t], a, bk_);
                mma16(s[2 * t + 1], a, bk_ + 2);
            }
        }
        __syncthreads();                  // all warps done reading Ks/Ds
        if (kt < 7) FILL_KD(kt + 1);      // single buffers; now safe

        // softmax in registers -> pack to PV A-fragments
        unsigned pP[4][4];
#pragma unroll
        for (int t = 0; t < 4; t++) {
            float e00 = __expf(s[2*t][0]),   e01 = __expf(s[2*t][1]);   // g,   k-lo
            float e02 = __expf(s[2*t][2]),   e03 = __expf(s[2*t][3]);   // g+8, k-lo
            float e10 = __expf(s[2*t+1][0]), e11 = __expf(s[2*t+1][1]); // g,   k-hi
            float e12 = __expf(s[2*t+1][2]), e13 = __expf(s[2*t+1][3]); // g+8, k-hi
            l_t[0] += e00 + e01 + e10 + e11;     // row g
            l_t[1] += e02 + e03 + e12 + e13;     // row g+8
            __half2 h0 = __floats2half2_rn(e00, e01);
            __half2 h1 = __floats2half2_rn(e02, e03);
            __half2 h2 = __floats2half2_rn(e10, e11);
            __half2 h3 = __floats2half2_rn(e12, e13);
            pP[t][0] = *(unsigned*)&h0;
            pP[t][1] = *(unsigned*)&h1;
            pP[t][2] = *(unsigned*)&h2;
            pP[t][3] = *(unsigned*)&h3;
        }

        // O += P @ V : 16 rows x 128 D, k = 64 (P from registers)
#pragma unroll
        for (int t = 0; t < 4; t++) {
#pragma unroll
            for (int nb = 0; nb < 8; nb++) {
                unsigned v[4];
                unsigned vaddr = smaddr(&Vs[(t * 16 + (lane & 15)) * QSTR +
                                            nb * 16 + ((lane >> 4) << 3)]);
                ldsm4t(v, vaddr);
                mma16(O[2 * nb], pP[t], v);
                mma16(O[2 * nb + 1], pP[t], v + 2);
            }
        }
    }

    // l: quad-lane reduce only (warp owns all 64 keys of each tile)
    float inv[2];
#pragma unroll
    for (int rr = 0; rr < 2; rr++) {
        float lv = l_t[rr];
        lv += __shfl_xor_sync(0xffffffffu, lv, 1);
        lv += __shfl_xor_sync(0xffffffffu, lv, 2);
        inv[rr] = (lv > 0.0f) ? 1.0f / lv : 0.0f;
    }

#pragma unroll
    for (int rr = 0; rr < 2; rr++) {
        int row = m0 + g + rr * 8;
        __half* orow = g_y1h + ((size_t)b * SEQ + q0 + row) * HD + h * DH;
#pragma unroll
        for (int nf = 0; nf < 16; nf++) {
            int col = nf * 8 + 2 * c;
            *(__half2*)&orow[col] = __floats2half2_rn(O[nf][rr * 2 + 0] * inv[rr],
                                                      O[nf][rr * 2 + 1] * inv[rr]);
        }
    }
}

// ---------------------------------------------------------------------------
// Output projection fp16, ldmatrix fragment loads
// grid NROWS/32 = 256, 512 thr; K staged 128 (8 stages), double-buf
// ---------------------------------------------------------------------------
#define OP_STG 21760
__global__ __launch_bounds__(512, 2) void oproj_kernel(
    const float* __restrict__ bo, const float* __restrict__ mask,
    float* __restrict__ out)
{
    extern __shared__ __half smh[];
    const int tid = threadIdx.x;
    const int wid = tid >> 5, lane = tid & 31;
    const int g = lane >> 2, c = lane & 3;
    const int wm = wid & 1, wn = wid >> 1;      // warp tile 16 x 16
    const int r0 = blockIdx.x * 32;
    const __half* abase = g_y1h + (size_t)r0 * HD;

    const int frow = tid >> 4, fc8 = (tid & 15) * 8;
#define OP_FILL(ks, buf) {                                                      \
        __half* As = smh + (buf) * OP_STG;                                      \
        __half* Bs = As + 4352;                                                 \
        const int k0 = (ks) * 128;                                              \
        cpa16(&As[frow * 136 + fc8], &abase[(size_t)frow * HD + k0 + fc8]);     \
        _Pragma("unroll")                                                       \
        for (int t = 0; t < 4; t++) {                                           \
            int row = frow + t * 32;                                            \
            cpa16(&Bs[row * 136 + fc8], &g_wot[(size_t)row * HD + k0 + fc8]);   \
        }                                                                       \
        CP_COMMIT(); }

    float acc[2][4];
#pragma unroll
    for (int nf = 0; nf < 2; nf++)
#pragma unroll
        for (int i = 0; i < 4; i++) acc[nf][i] = 0.0f;

    // ldmatrix lane offsets (within-tile)
    const unsigned aoff = ((wm * 16 + (lane & 7) + (((lane >> 3) & 1) << 3)) * 136 +
                           ((lane >> 4) << 3)) * 2;
    const unsigned boff = ((wn * 16 + (lane & 7) + ((lane >> 4) << 3)) * 136 +
                           (((lane >> 3) & 1) << 3)) * 2;

    OP_FILL(0, 0);
    for (int ks = 0; ks < 8; ks++) {
        if (ks < 7) { OP_FILL(ks + 1, (ks + 1) & 1); CP_WAIT(1); }
        else        { CP_WAIT(0); }
        __syncthreads();
        const __half* As = smh + (ks & 1) * OP_STG;
        const __half* Bs = As + 4352;
        const unsigned aA = smaddr(As) + aoff;
        const unsigned bB = smaddr(Bs) + boff;
#pragma unroll
        for (int kb = 0; kb < 8; kb++) {
            unsigned a[4], bb[4];
            ldsm4(a, aA + kb * 32);
            ldsm4(bb, bB + kb * 32);
            mma16(acc[0], a, bb);
            mma16(acc[1], a, bb + 2);
        }
        __syncthreads();
    }

#pragma unroll
    for (int rr = 0; rr < 2; rr++) {
        int row = r0 + wm * 16 + g + rr * 8;
        float mm = mask[row];
#pragma unroll
        for (int nf = 0; nf < 2; nf++) {
            int col = wn * 16 + nf * 8 + 2 * c;
            float v0 = (acc[nf][rr * 2 + 0] + bo[col]) * mm;
            float v1 = (acc[nf][rr * 2 + 1] + bo[col + 1]) * mm;
            *(float2*)&out[(size_t)row * DH + col] = make_float2(v0, v1);
        }
    }
}

// ---------------------------------------------------------------------------
extern "C" void kernel_launch(void* const* d_in, const int* in_sizes, int n_in,
                              void* d_out, int out_size)
{
    const float* x    = (const float*)d_in[0];
    const float* dist = (const float*)d_in[1];
    const float* mask = (const float*)d_in[2];
    const float* Wq   = (const float*)d_in[3];
    const float* bq   = (const float*)d_in[4];
    const float* Wk   = (const float*)d_in[5];
    const float* bk   = (const float*)d_in[6];
    const float* Wv   = (const float*)d_in[7];
    const float* bv   = (const float*)d_in[8];
    const float* Wo   = (const float*)d_in[9];
    const float* bo   = (const float*)d_in[10];
    float* out = (float*)d_out;

    const int proj_smem = (128 * PRSTR + 64 * PRSTR) * 2;              // 52224
    const int attn_smem = (128*QSTR + 64*QSTR + 2*64*QSTR + 128*DSTR) * 2; // 105472
    const int op_smem   = OP_STG * 2 * 2;                              // 87040

    static cudaStream_t s1;
    static cudaEvent_t ev_fork, ev_join;
    static int configured = 0;
    if (!configured) {
        cudaFuncSetAttribute(proj_kernel, cudaFuncAttributeMaxDynamicSharedMemorySize, proj_smem);
        cudaFuncSetAttribute(attn_kernel, cudaFuncAttributeMaxDynamicSharedMemorySize, attn_smem);
        cudaFuncSetAttribute(oproj_kernel, cudaFuncAttributeMaxDynamicSharedMemorySize, op_smem);
        cudaStreamCreateWithFlags(&s1, cudaStreamNonBlocking);
        cudaEventCreateWithFlags(&ev_fork, cudaEventDisableTiming);
        cudaEventCreateWithFlags(&ev_join, cudaEventDisableTiming);
        configured = 1;
    }

    // fork: dprep (only consumer is attn) runs concurrently with prep/wtrans/proj
    cudaEventRecord(ev_fork, 0);
    cudaStreamWaitEvent(s1, ev_fork, 0);
    dprep_kernel<<<4096, 256, 0, s1>>>(dist, mask);
    cudaEventRecord(ev_join, s1);

    prep_kernel<<<1024, 256>>>(x);
    wtrans_kernel<<<dim3(32, 32, 4), dim3(32, 8)>>>(Wq, Wk, Wv, Wo);
    proj_kernel<<<dim3(HD/64, NROWS/128, 3), 256, proj_smem>>>(mask, bq, bk, bv);

    // join: attn needs g_dh
    cudaStreamWaitEvent(0, ev_join, 0);
    attn_kernel<<<dim3(SEQ/128, BB*NH), 256, attn_smem>>>();
    oproj_kernel<<<dim3(NROWS/32), 512, op_smem>>>(bo, mask, out);
}

// round 17
// speedup vs baseline: 1.3470x; 1.0230x over previous
#include <cuda_runtime.h>
#include <cuda_fp16.h>

#define BB   16
#define SEQ  512
#define NH   8
#define DH   128
#define HD   1024
#define NROWS (BB*SEQ)            // 8192
#define SCALE 0.08838834764831843f

// Scratch (no device allocation allowed)
__device__ __half g_q  [BB*NH*SEQ*DH]; // [B,H,N,D] masked*scaled fp16
__device__ __half g_k  [BB*NH*SEQ*DH]; // [B,H,N,D] masked fp16
__device__ __half g_v  [BB*NH*SEQ*DH]; // [B,H,N,D] masked fp16
__device__ __half g_dh [BB*SEQ*SEQ];   // dist + key-mask(-1e9), fp16
__device__ __half g_y1h[NROWS*HD];     // [B,N,H*D] attn out fp16
__device__ __half g_xh [NROWS*DH];     // x fp16
__device__ __half g_wqt[HD*DH];        // Wq^T [n][k] fp16
__device__ __half g_wkt[HD*DH];
__device__ __half g_wvt[HD*DH];
__device__ __half g_wot[DH*HD];        // Wo^T [n=128][k=1024] fp16

__device__ __forceinline__ void cpa16(void* dst_smem, const void* src_gmem) {
    unsigned s = (unsigned)__cvta_generic_to_shared(dst_smem);
    asm volatile("cp.async.cg.shared.global [%0], [%1], 16;\n" :: "r"(s), "l"(src_gmem));
}
#define CP_COMMIT() asm volatile("cp.async.commit_group;\n")
#define CP_WAIT(n)  asm volatile("cp.async.wait_group %0;\n" :: "n"(n))

// fp16 k16 mma, fp32 accum
__device__ __forceinline__ void mma16(float* d, const unsigned* a, const unsigned* b) {
    asm volatile(
        "mma.sync.aligned.m16n8k16.row.col.f32.f16.f16.f32 "
        "{%0,%1,%2,%3}, {%4,%5,%6,%7}, {%8,%9}, {%0,%1,%2,%3};"
        : "+f"(d[0]), "+f"(d[1]), "+f"(d[2]), "+f"(d[3])
        : "r"(a[0]), "r"(a[1]), "r"(a[2]), "r"(a[3]), "r"(b[0]), "r"(b[1]));
}
__device__ __forceinline__ unsigned smaddr(const void* p) {
    return (unsigned)__cvta_generic_to_shared(p);
}
__device__ __forceinline__ void ldsm4(unsigned* r, unsigned a) {
    asm volatile("ldmatrix.sync.aligned.m8n8.x4.shared.b16 {%0,%1,%2,%3}, [%4];"
        : "=r"(r[0]), "=r"(r[1]), "=r"(r[2]), "=r"(r[3]) : "r"(a));
}
__device__ __forceinline__ void ldsm4t(unsigned* r, unsigned a) {
    asm volatile("ldmatrix.sync.aligned.m8n8.x4.trans.shared.b16 {%0,%1,%2,%3}, [%4];"
        : "=r"(r[0]), "=r"(r[1]), "=r"(r[2]), "=r"(r[3]) : "r"(a));
}

// ---------------------------------------------------------------------------
// prep: x -> fp16. grid 1024 x 256
// ---------------------------------------------------------------------------
__global__ void prep_kernel(const float* __restrict__ x)
{
    int i = blockIdx.x * 256 + threadIdx.x;       // float4 index
    if (i < NROWS*DH/4) {
        float4 v = ((const float4*)x)[i];
        ((__half2*)g_xh)[i * 2 + 0] = __floats2half2_rn(v.x, v.y);
        ((__half2*)g_xh)[i * 2 + 1] = __floats2half2_rn(v.z, v.w);
    }
}

// ---------------------------------------------------------------------------
// weight transpose -> fp16: W[R=k][C=n] f32 -> Wt[C][R] h16. grid (32,32,4)
// ---------------------------------------------------------------------------
__global__ void wtrans_kernel(const float* __restrict__ Wq, const float* __restrict__ Wk,
                              const float* __restrict__ Wv, const float* __restrict__ Wo)
{
    __shared__ float t[32][33];
    const int z = blockIdx.z;
    const float* src = (z == 0) ? Wq : (z == 1) ? Wk : (z == 2) ? Wv : Wo;
    __half* dst = (z == 0) ? g_wqt : (z == 1) ? g_wkt : (z == 2) ? g_wvt : g_wot;
    const int R = (z < 3) ? DH : HD;
    const int C = (z < 3) ? HD : DH;
    if ((int)blockIdx.x * 32 >= C || (int)blockIdx.y * 32 >= R) return;
    const int tx = threadIdx.x, ty = threadIdx.y;
    const int r = blockIdx.y * 32, c = blockIdx.x * 32;
#pragma unroll
    for (int j = 0; j < 4; j++)
        t[ty + j*8][tx] = src[(size_t)(r + ty + j*8) * C + c + tx];
    __syncthreads();
#pragma unroll
    for (int j = 0; j < 4; j++)
        dst[(size_t)(c + ty + j*8) * R + r + tx] = __float2half_rn(t[tx][ty + j*8]);
}

// ---------------------------------------------------------------------------
// dprep: g_dh = fp16(dist + (mask[key]? 0 : -1e9)). grid 4096 x 256
// ---------------------------------------------------------------------------
__global__ void dprep_kernel(const float* __restrict__ dist,
                             const float* __restrict__ mask)
{
    size_t i4 = (size_t)blockIdx.x * 256 + threadIdx.x;
    float4 v = ((const float4*)dist)[i4];
    int m = (int)(i4 & 127) * 4;
    int b = (int)(i4 >> 16);
    const float* mrow = mask + b * SEQ;
    float a0 = v.x + ((mrow[m + 0] == 0.0f) ? -1e9f : 0.0f);
    float a1 = v.y + ((mrow[m + 1] == 0.0f) ? -1e9f : 0.0f);
    float a2 = v.z + ((mrow[m + 2] == 0.0f) ? -1e9f : 0.0f);
    float a3 = v.w + ((mrow[m + 3] == 0.0f) ? -1e9f : 0.0f);
    ((__half2*)g_dh)[i4 * 2 + 0] = __floats2half2_rn(a0, a1);
    ((__half2*)g_dh)[i4 * 2 + 1] = __floats2half2_rn(a2, a3);
}

// ---------------------------------------------------------------------------
// FUSED QKV projection fp16: one CTA computes q, k AND v for its (r0, c0)
// tile. x tile loaded ONCE; 3 W tiles prefetched as separate commit groups
// up front; wait(2)/wait(1)/wait(0) peels one group per sel.
// grid (HD/64 = 16, NROWS/128 = 64), 256 thr (8 warps: wm 0..3, wn 0..1)
// smem: As[128][136] + 3 x Bs[64][136] = 87040 B  -> 2 CTAs/SM
// ---------------------------------------------------------------------------
#define PRSTR 136
__global__ __launch_bounds__(256, 2) void proj_kernel(
    const float* __restrict__ mask,
    const float* __restrict__ bq, const float* __restrict__ bk,
    const float* __restrict__ bv)
{
    extern __shared__ __half smh[];
    __half* As = smh;                        // [128][136]
    __half* Bs0 = As + 128 * PRSTR;          // 3 x [64][136]
    const int tid = threadIdx.x;
    const int wid = tid >> 5, lane = tid & 31;
    const int g = lane >> 2, c = lane & 3;
    const int wm = wid & 3, wn = wid >> 2;   // warp tile 32 x 32
    const int c0 = blockIdx.x * 64;
    const int r0 = blockIdx.y * 128;
    const __half* xbase = g_xh + (size_t)r0 * DH;

    // fills: As + Wq group, then Wk group, then Wv group (3 groups in flight)
    const int frow = tid >> 4, fc8 = (tid & 15) * 8;
    {
#pragma unroll
        for (int t = 0; t < 8; t++) {
            int row = frow + t * 16;
            cpa16(&As[row * PRSTR + fc8], &xbase[(size_t)row * DH + fc8]);
        }
        const __half* wq = g_wqt + (size_t)c0 * DH;
#pragma unroll
        for (int t = 0; t < 4; t++) {
            int row = frow + t * 16;
            cpa16(&Bs0[row * PRSTR + fc8], &wq[(size_t)row * DH + fc8]);
        }
        CP_COMMIT();
        const __half* wk = g_wkt + (size_t)c0 * DH;
#pragma unroll
        for (int t = 0; t < 4; t++) {
            int row = frow + t * 16;
            cpa16(&Bs0[(64 * PRSTR) + row * PRSTR + fc8], &wk[(size_t)row * DH + fc8]);
        }
        CP_COMMIT();
        const __half* wv = g_wvt + (size_t)c0 * DH;
#pragma unroll
        for (int t = 0; t < 4; t++) {
            int row = frow + t * 16;
            cpa16(&Bs0[(128 * PRSTR) + row * PRSTR + fc8], &wv[(size_t)row * DH + fc8]);
        }
        CP_COMMIT();
    }

    // ldmatrix base addresses
    unsigned aA[2];
#pragma unroll
    for (int mf = 0; mf < 2; mf++)
        aA[mf] = smaddr(&As[(wm * 32 + mf * 16 + (lane & 7) +
                             (((lane >> 3) & 1) << 3)) * PRSTR +
                            ((lane >> 4) << 3)]);
    const unsigned bBoff = ((wn * 32 + (lane & 7) + ((lane >> 4) << 3)) * PRSTR +
                            (((lane >> 3) & 1) << 3)) * 2;
    const unsigned bBoff2 = (16 * PRSTR) * 2;     // +16 cols within sel's Bs

    bool synced = false;
    for (int sel = 0; sel < 3; sel++) {
        if (sel == 0)      CP_WAIT(2);
        else if (sel == 1) CP_WAIT(1);
        else               CP_WAIT(0);
        if (!synced) { __syncthreads(); synced = true; }
        // (later waits only ADD completed groups; no cross-thread hazard:
        //  each sel's Bs region is written before its group commit and read
        //  only after the corresponding wait has drained in EVERY thread —
        //  guaranteed because wait(n) per-thread covers its own fills and
        //  smem writes by cp.async are made visible by the first barrier +
        //  per-thread waits. To stay strictly safe we barrier each sel.)
        __syncthreads();

        const unsigned bB = smaddr(Bs0 + sel * 64 * PRSTR) + bBoff;
        const float* bias = (sel == 0) ? bq : (sel == 1) ? bk : bv;
        __half* out = (sel == 0) ? g_q : (sel == 1) ? g_k : g_v;
        const float extra = (sel == 0) ? SCALE : 1.0f;

        float acc[2][4][4];
#pragma unroll
        for (int mf = 0; mf < 2; mf++)
#pragma unroll
            for (int nf = 0; nf < 4; nf++)
#pragma unroll
                for (int i = 0; i < 4; i++) acc[mf][nf][i] = 0.0f;

#pragma unroll
        for (int kb = 0; kb < 8; kb++) {
            unsigned a0[4], a1[4];
            ldsm4(a0, aA[0] + kb * 32);
            ldsm4(a1, aA[1] + kb * 32);
            unsigned bb0[4], bb1[4];
            ldsm4(bb0, bB + kb * 32);
            ldsm4(bb1, bB + bBoff2 + kb * 32);
            mma16(acc[0][0], a0, bb0);
            mma16(acc[0][1], a0, bb0 + 2);
            mma16(acc[1][0], a1, bb0);
            mma16(acc[1][1], a1, bb0 + 2);
            mma16(acc[0][2], a0, bb1);
            mma16(acc[0][3], a0, bb1 + 2);
            mma16(acc[1][2], a1, bb1);
            mma16(acc[1][3], a1, bb1 + 2);
        }

#pragma unroll
        for (int mf = 0; mf < 2; mf++) {
#pragma unroll
            for (int rr = 0; rr < 2; rr++) {
                int row = r0 + wm * 32 + mf * 16 + g + rr * 8;
                int bI = row >> 9, n = row & 511;
                float mm = mask[row] * extra;
#pragma unroll
                for (int nf = 0; nf < 4; nf++) {
                    int col = c0 + wn * 32 + nf * 8 + 2 * c;
                    int h = col >> 7, d = col & 127;
                    float v0 = (acc[mf][nf][rr * 2 + 0] + bias[col]) * mm;
                    float v1 = (acc[mf][nf][rr * 2 + 1] + bias[col + 1]) * mm;
                    *(__half2*)&out[(((size_t)bI * NH + h) * SEQ + n) * DH + d] =
                        __floats2half2_rn(v0, v1);
                }
            }
        }
    }
}

// ---------------------------------------------------------------------------
// Flash attention fp16, FA2-style (unchanged from R16)
// ---------------------------------------------------------------------------
#define QSTR 136
#define DSTR 72
__global__ __launch_bounds__(256, 2) void attn_kernel()
{
    extern __shared__ __half smh[];
    __half* Qs = smh;                    // [128][136]
    __half* Ks = Qs + 128 * QSTR;        // [64][136] single
    __half* V2 = Ks + 64 * QSTR;         // 2 x [64][136]
    __half* Ds = V2 + 2 * 64 * QSTR;     // [128][72] single

    const int tid = threadIdx.x;
    const int wid = tid >> 5, lane = tid & 31;
    const int g = lane >> 2, c = lane & 3;
    const int bh = blockIdx.y;
    const int b = bh >> 3, h = bh & 7;
    const int q0 = blockIdx.x * 128;
    const int m0 = wid * 16;             // warp owns rows m0..m0+15

    const __half* qbase = g_q + (size_t)bh * SEQ * DH;
    const __half* kbase = g_k + (size_t)bh * SEQ * DH;
    const __half* vbase = g_v + (size_t)bh * SEQ * DH;
    const __half* dbase = g_dh + ((size_t)b * SEQ + q0) * SEQ;

    const int frow = tid >> 4, fc8 = (tid & 15) * 8;   // K/V: 64 rows x 16 chunks
    const int drow = tid >> 3, dc8 = (tid & 7) * 8;    // D: 128 rows x 8 chunks

#define FILL_KD(kt) {                                                           \
        _Pragma("unroll")                                                       \
        for (int t = 0; t < 4; t++) {                                           \
            int key = frow + t * 16;                                            \
            cpa16(&Ks[key * QSTR + fc8],                                        \
                  &kbase[(size_t)((kt) * 64 + key) * DH + fc8]);                \
        }                                                                       \
        _Pragma("unroll")                                                       \
        for (int t = 0; t < 4; t++) {                                           \
            int row = drow + t * 32;                                            \
            cpa16(&Ds[row * DSTR + dc8],                                        \
                  &dbase[(size_t)row * SEQ + (kt) * 64 + dc8]);                 \
        }                                                                       \
        CP_COMMIT(); }
#define FILL_V(kt) {                                                            \
        __half* Vs = V2 + ((kt) & 1) * 64 * QSTR;                               \
        _Pragma("unroll")                                                       \
        for (int t = 0; t < 4; t++) {                                           \
            int key = frow + t * 16;                                            \
            cpa16(&Vs[key * QSTR + fc8],                                        \
                  &vbase[(size_t)((kt) * 64 + key) * DH + fc8]);                \
        }                                                                       \
        CP_COMMIT(); }

    // prologue: Q + K(0) + D(0), then V(0)
    {
#pragma unroll
        for (int t = 0; t < 8; t++) {
            int row = frow + t * 16;
            cpa16(&Qs[row * QSTR + fc8], &qbase[(size_t)(q0 + row) * DH + fc8]);
        }
        FILL_KD(0);
        FILL_V(0);
    }

    float O[16][4];
#pragma unroll
    for (int nf = 0; nf < 16; nf++)
#pragma unroll
        for (int i = 0; i < 4; i++) O[nf][i] = 0.0f;
    float l_t[2] = {0.0f, 0.0f};

    // ldmatrix lane coords
    const int arow = m0 + (lane & 7) + (((lane >> 3) & 1) << 3);
    const int akoff = (lane >> 4) << 3;
    const unsigned aQ = smaddr(&Qs[arow * QSTR + akoff]);
    unsigned bK[4];
#pragma unroll
    for (int t = 0; t < 4; t++)
        bK[t] = smaddr(&Ks[(t * 16 + (lane & 7) + ((lane >> 4) << 3)) * QSTR +
                           (((lane >> 3) & 1) << 3)]);

    for (int kt = 0; kt < 8; kt++) {
        const __half* Vs = V2 + (kt & 1) * 64 * QSTR;
        CP_WAIT(0);                       // K/D(kt) + V(kt) landed
        __syncthreads();                  // all warps past PV(kt-1)
        if (kt < 7) FILL_V(kt + 1);       // other V buffer; safe

        // S init from dist tile (dist+mask pre-fused fp16)
        float s[8][4];
#pragma unroll
        for (int nf = 0; nf < 8; nf++) {
            int gcol = nf * 8 + 2 * c;
            float2 d0 = __half22float2(*(const __half2*)&Ds[(m0 + g) * DSTR + gcol]);
            float2 d1 = __half22float2(*(const __half2*)&Ds[(m0 + g + 8) * DSTR + gcol]);
            s[nf][0] = d0.x; s[nf][1] = d0.y;
            s[nf][2] = d1.x; s[nf][3] = d1.y;
        }
        // S += Q @ K^T : 16 rows x 64 keys, k = 128
#pragma unroll
        for (int kb = 0; kb < 8; kb++) {
            unsigned a[4];
            ldsm4(a, aQ + kb * 32);
#pragma unroll
            for (int t = 0; t < 4; t++) {
                unsigned bk_[4];
                ldsm4(bk_, bK[t] + kb * 32);
                mma16(s[2 * t], a, bk_);
                mma16(s[2 * t + 1], a, bk_ + 2);
            }
        }
        __syncthreads();                  // all warps done reading Ks/Ds
        if (kt < 7) FILL_KD(kt + 1);      // single buffers; now safe

        // softmax in registers -> pack to PV A-fragments
        unsigned pP[4][4];
#pragma unroll
        for (int t = 0; t < 4; t++) {
            float e00 = __expf(s[2*t][0]),   e01 = __expf(s[2*t][1]);   // g,   k-lo
            float e02 = __expf(s[2*t][2]),   e03 = __expf(s[2*t][3]);   // g+8, k-lo
            float e10 = __expf(s[2*t+1][0]), e11 = __expf(s[2*t+1][1]); // g,   k-hi
            float e12 = __expf(s[2*t+1][2]), e13 = __expf(s[2*t+1][3]); // g+8, k-hi
            l_t[0] += e00 + e01 + e10 + e11;     // row g
            l_t[1] += e02 + e03 + e12 + e13;     // row g+8
            __half2 h0 = __floats2half2_rn(e00, e01);
            __half2 h1 = __floats2half2_rn(e02, e03);
            __half2 h2 = __floats2half2_rn(e10, e11);
            __half2 h3 = __floats2half2_rn(e12, e13);
            pP[t][0] = *(unsigned*)&h0;
            pP[t][1] = *(unsigned*)&h1;
            pP[t][2] = *(unsigned*)&h2;
            pP[t][3] = *(unsigned*)&h3;
        }

        // O += P @ V : 16 rows x 128 D, k = 64 (P from registers)
#pragma unroll
        for (int t = 0; t < 4; t++) {
#pragma unroll
            for (int nb = 0; nb < 8; nb++) {
                unsigned v[4];
                unsigned vaddr = smaddr(&Vs[(t * 16 + (lane & 15)) * QSTR +
                                            nb * 16 + ((lane >> 4) << 3)]);
                ldsm4t(v, vaddr);
                mma16(O[2 * nb], pP[t], v);
                mma16(O[2 * nb + 1], pP[t], v + 2);
            }
        }
    }

    // l: quad-lane reduce only (warp owns all 64 keys of each tile)
    float inv[2];
#pragma unroll
    for (int rr = 0; rr < 2; rr++) {
        float lv = l_t[rr];
        lv += __shfl_xor_sync(0xffffffffu, lv, 1);
        lv += __shfl_xor_sync(0xffffffffu, lv, 2);
        inv[rr] = (lv > 0.0f) ? 1.0f / lv : 0.0f;
    }

#pragma unroll
    for (int rr = 0; rr < 2; rr++) {
        int row = m0 + g + rr * 8;
        __half* orow = g_y1h + ((size_t)b * SEQ + q0 + row) * HD + h * DH;
#pragma unroll
        for (int nf = 0; nf < 16; nf++) {
            int col = nf * 8 + 2 * c;
            *(__half2*)&orow[col] = __floats2half2_rn(O[nf][rr * 2 + 0] * inv[rr],
                                                      O[nf][rr * 2 + 1] * inv[rr]);
        }
    }
}

// ---------------------------------------------------------------------------
// Output projection fp16, ldmatrix fragment loads (unchanged from R16)
// ---------------------------------------------------------------------------
#define OP_STG 21760
__global__ __launch_bounds__(512, 2) void oproj_kernel(
    const float* __restrict__ bo, const float* __restrict__ mask,
    float* __restrict__ out)
{
    extern __shared__ __half smh[];
    const int tid = threadIdx.x;
    const int wid = tid >> 5, lane = tid & 31;
    const int g = lane >> 2, c = lane & 3;
    const int wm = wid & 1, wn = wid >> 1;      // warp tile 16 x 16
    const int r0 = blockIdx.x * 32;
    const __half* abase = g_y1h + (size_t)r0 * HD;

    const int frow = tid >> 4, fc8 = (tid & 15) * 8;
#define OP_FILL(ks, buf) {                                                      \
        __half* As = smh + (buf) * OP_STG;                                      \
        __half* Bs = As + 4352;                                                 \
        const int k0 = (ks) * 128;                                              \
        cpa16(&As[frow * 136 + fc8], &abase[(size_t)frow * HD + k0 + fc8]);     \
        _Pragma("unroll")                                                       \
        for (int t = 0; t < 4; t++) {                                           \
            int row = frow + t * 32;                                            \
            cpa16(&Bs[row * 136 + fc8], &g_wot[(size_t)row * HD + k0 + fc8]);   \
        }                                                                       \
        CP_COMMIT(); }

    float acc[2][4];
#pragma unroll
    for (int nf = 0; nf < 2; nf++)
#pragma unroll
        for (int i = 0; i < 4; i++) acc[nf][i] = 0.0f;

    const unsigned aoff = ((wm * 16 + (lane & 7) + (((lane >> 3) & 1) << 3)) * 136 +
                           ((lane >> 4) << 3)) * 2;
    const unsigned boff = ((wn * 16 + (lane & 7) + ((lane >> 4) << 3)) * 136 +
                           (((lane >> 3) & 1) << 3)) * 2;

    OP_FILL(0, 0);
    for (int ks = 0; ks < 8; ks++) {
        if (ks < 7) { OP_FILL(ks + 1, (ks + 1) & 1); CP_WAIT(1); }
        else        { CP_WAIT(0); }
        __syncthreads();
        const __half* As = smh + (ks & 1) * OP_STG;
        const __half* Bs = As + 4352;
        const unsigned aA = smaddr(As) + aoff;
        const unsigned bB = smaddr(Bs) + boff;
#pragma unroll
        for (int kb = 0; kb < 8; kb++) {
            unsigned a[4], bb[4];
            ldsm4(a, aA + kb * 32);
            ldsm4(bb, bB + kb * 32);
            mma16(acc[0], a, bb);
            mma16(acc[1], a, bb + 2);
        }
        __syncthreads();
    }

#pragma unroll
    for (int rr = 0; rr < 2; rr++) {
        int row = r0 + wm * 16 + g + rr * 8;
        float mm = mask[row];
#pragma unroll
        for (int nf = 0; nf < 2; nf++) {
            int col = wn * 16 + nf * 8 + 2 * c;
            float v0 = (acc[nf][rr * 2 + 0] + bo[col]) * mm;
            float v1 = (acc[nf][rr * 2 + 1] + bo[col + 1]) * mm;
            *(float2*)&out[(size_t)row * DH + col] = make_float2(v0, v1);
        }
    }
}

// ---------------------------------------------------------------------------
extern "C" void kernel_launch(void* const* d_in, const int* in_sizes, int n_in,
                              void* d_out, int out_size)
{
    const float* x    = (const float*)d_in[0];
    const float* dist = (const float*)d_in[1];
    const float* mask = (const float*)d_in[2];
    const float* Wq   = (const float*)d_in[3];
    const float* bq   = (const float*)d_in[4];
    const float* Wk   = (const float*)d_in[5];
    const float* bk   = (const float*)d_in[6];
    const float* Wv   = (const float*)d_in[7];
    const float* bv   = (const float*)d_in[8];
    const float* Wo   = (const float*)d_in[9];
    const float* bo   = (const float*)d_in[10];
    float* out = (float*)d_out;

    const int proj_smem = (128 * PRSTR + 3 * 64 * PRSTR) * 2;          // 87040
    const int attn_smem = (128*QSTR + 64*QSTR + 2*64*QSTR + 128*DSTR) * 2; // 105472
    const int op_smem   = OP_STG * 2 * 2;                              // 87040

    static cudaStream_t s1;
    static cudaEvent_t ev_fork, ev_join;
    static int configured = 0;
    if (!configured) {
        cudaFuncSetAttribute(proj_kernel, cudaFuncAttributeMaxDynamicSharedMemorySize, proj_smem);
        cudaFuncSetAttribute(attn_kernel, cudaFuncAttributeMaxDynamicSharedMemorySize, attn_smem);
        cudaFuncSetAttribute(oproj_kernel, cudaFuncAttributeMaxDynamicSharedMemorySize, op_smem);
        cudaStreamCreateWithFlags(&s1, cudaStreamNonBlocking);
        cudaEventCreateWithFlags(&ev_fork, cudaEventDisableTiming);
        cudaEventCreateWithFlags(&ev_join, cudaEventDisableTiming);
        configured = 1;
    }

    // fork: dprep (only consumer is attn) runs concurrently with prep/wtrans/proj
    cudaEventRecord(ev_fork, 0);
    cudaStreamWaitEvent(s1, ev_fork, 0);
    dprep_kernel<<<4096, 256, 0, s1>>>(dist, mask);
    cudaEventRecord(ev_join, s1);

    prep_kernel<<<1024, 256>>>(x);
    wtrans_kernel<<<dim3(32, 32, 4), dim3(32, 8)>>>(Wq, Wk, Wv, Wo);
    proj_kernel<<<dim3(HD/64, NROWS/128), 256, proj_smem>>>(mask, bq, bk, bv);

    // join: attn needs g_dh
    cudaStreamWaitEvent(0, ev_join, 0);
    attn_kernel<<<dim3(SEQ/128, BB*NH), 256, attn_smem>>>();
    oproj_kernel<<<dim3(NROWS/32), 512, op_smem>>>(bo, mask, out);
}